// round 1
// baseline (speedup 1.0000x reference)
#include <cuda_runtime.h>

#define TT 4
#define BB 4
#define NN 1024
#define DD 512
#define HH 8
#define HDIM 64
#define MM (TT*BB*NN)   // 16384 total rows
#define EPSV 1e-6f

// Scratch (device globals: allocation-free rule)
__device__ float g_q[MM * DD];
__device__ float g_k[MM * DD];
__device__ float g_v[MM * DD];
__device__ float g_ctx[MM * DD];

// ---------------------------------------------------------------------------
// GEMM: C[M, 512] = A[M, 512] @ W[512, 512]^T + bias
// Tiles: BM=128, BN=128, BK=8; 256 threads; 8x8 register tile per thread.
// ---------------------------------------------------------------------------
__global__ __launch_bounds__(256) void gemm_bias_kernel(
    const float* __restrict__ A, const float* __restrict__ W,
    const float* __restrict__ bias, float* __restrict__ C)
{
    __shared__ float As[8][128];
    __shared__ float Ws[8][128];

    const int tid = threadIdx.x;
    const int m0 = blockIdx.y * 128;
    const int n0 = blockIdx.x * 128;
    const int tx = tid & 15;
    const int ty = tid >> 4;

    const int lr = tid >> 1;          // 0..127 (row within tile)
    const int lc = (tid & 1) * 4;     // 0 or 4 (k offset, float4)
    const float* Ap = A + (size_t)(m0 + lr) * DD + lc;
    const float* Wp = W + (size_t)(n0 + lr) * DD + lc;

    float acc[8][8];
    #pragma unroll
    for (int i = 0; i < 8; i++)
        #pragma unroll
        for (int j = 0; j < 8; j++)
            acc[i][j] = 0.f;

    for (int k0 = 0; k0 < DD; k0 += 8) {
        float4 av = *(const float4*)(Ap + k0);
        float4 wv = *(const float4*)(Wp + k0);
        __syncthreads();
        As[lc + 0][lr] = av.x; As[lc + 1][lr] = av.y;
        As[lc + 2][lr] = av.z; As[lc + 3][lr] = av.w;
        Ws[lc + 0][lr] = wv.x; Ws[lc + 1][lr] = wv.y;
        Ws[lc + 2][lr] = wv.z; Ws[lc + 3][lr] = wv.w;
        __syncthreads();

        #pragma unroll
        for (int kk = 0; kk < 8; kk++) {
            float4 a0 = *(const float4*)&As[kk][ty * 8];
            float4 a1 = *(const float4*)&As[kk][ty * 8 + 4];
            float4 b0 = *(const float4*)&Ws[kk][tx * 8];
            float4 b1 = *(const float4*)&Ws[kk][tx * 8 + 4];
            float a[8] = {a0.x, a0.y, a0.z, a0.w, a1.x, a1.y, a1.z, a1.w};
            float b[8] = {b0.x, b0.y, b0.z, b0.w, b1.x, b1.y, b1.z, b1.w};
            #pragma unroll
            for (int i = 0; i < 8; i++)
                #pragma unroll
                for (int j = 0; j < 8; j++)
                    acc[i][j] += a[i] * b[j];
        }
    }

    #pragma unroll
    for (int i = 0; i < 8; i++) {
        const int m = m0 + ty * 8 + i;
        #pragma unroll
        for (int j = 0; j < 8; j += 4) {
            const int n = n0 + tx * 8 + j;
            float4 o;
            o.x = acc[i][j + 0] + bias[n + 0];
            o.y = acc[i][j + 1] + bias[n + 1];
            o.z = acc[i][j + 2] + bias[n + 2];
            o.w = acc[i][j + 3] + bias[n + 3];
            *(float4*)&C[(size_t)m * DD + n] = o;
        }
    }
}

// ---------------------------------------------------------------------------
// Fused relu-normalized attention, one (tb, head, q-tile of 64) per block.
// Single pass: acc += relu(QK^T/8) * V ; denom += relu(QK^T/8). ctx = acc/(denom+eps).
// smem layouts chosen for conflict-free hot-loop LDS:
//   Qst[c][q]   (transposed, loaded once per block)
//   Ks[kk][c], Vs[kk][d] (natural)
//   Ss[kk][q]   (scores stored k-major so both GEMM phases read float4/broadcast)
// ---------------------------------------------------------------------------
#define ATTN_SMEM ((4 * 64 * 64 + 64) * 4)

__global__ __launch_bounds__(256) void attn_kernel(
    const float* __restrict__ qg, const float* __restrict__ kg,
    const float* __restrict__ vg, float* __restrict__ ctx)
{
    extern __shared__ float sm[];
    float* Qst   = sm;                // [64][64]  [c][q]
    float* Ks    = sm + 64 * 64;      // [kk][c]
    float* Vs    = sm + 2 * 64 * 64;  // [kk][d]
    float* Ss    = sm + 3 * 64 * 64;  // [kk][q]
    float* denom = sm + 4 * 64 * 64;  // [64]

    const int tid = threadIdx.x;
    const int tx = tid & 15;
    const int ty = tid >> 4;
    const int qt = blockIdx.x;        // 0..15
    const int h  = blockIdx.y;        // 0..7
    const int tb = blockIdx.z;        // 0..15
    const size_t rowbase = (size_t)tb * NN;
    const int col0 = h * HDIM;

    // Load Q tile transposed into Qst[c][q] (once per block)
    {
        const int r  = tid >> 4;          // 0..15
        const int c4 = (tid & 15) * 4;    // 0..60
        #pragma unroll
        for (int rr = 0; rr < 64; rr += 16) {
            const int qq = rr + r;
            float4 t = *(const float4*)&qg[(rowbase + qt * 64 + qq) * DD + col0 + c4];
            Qst[(c4 + 0) * 64 + qq] = t.x;
            Qst[(c4 + 1) * 64 + qq] = t.y;
            Qst[(c4 + 2) * 64 + qq] = t.z;
            Qst[(c4 + 3) * 64 + qq] = t.w;
        }
    }
    if (tid < 64) denom[tid] = 0.f;

    float acc[4][4];
    #pragma unroll
    for (int i = 0; i < 4; i++)
        #pragma unroll
        for (int j = 0; j < 4; j++)
            acc[i][j] = 0.f;

    for (int kt = 0; kt < 16; kt++) {
        __syncthreads();  // protect Ks/Vs/Ss from previous iteration readers
        {
            const int r  = tid >> 4;
            const int c4 = (tid & 15) * 4;
            #pragma unroll
            for (int rr = 0; rr < 64; rr += 16) {
                const int kkr = rr + r;
                float4 tk = *(const float4*)&kg[(rowbase + kt * 64 + kkr) * DD + col0 + c4];
                float4 tv = *(const float4*)&vg[(rowbase + kt * 64 + kkr) * DD + col0 + c4];
                *(float4*)&Ks[kkr * 64 + c4] = tk;
                *(float4*)&Vs[kkr * 64 + c4] = tv;
            }
        }
        __syncthreads();

        // S'[kk][q]: thread owns kk = ty*4+i, q = tx*4+j
        float s[4][4];
        #pragma unroll
        for (int i = 0; i < 4; i++)
            #pragma unroll
            for (int j = 0; j < 4; j++)
                s[i][j] = 0.f;

        #pragma unroll 8
        for (int c = 0; c < 64; c++) {
            float a0 = Ks[(ty * 4 + 0) * 64 + c];
            float a1 = Ks[(ty * 4 + 1) * 64 + c];
            float a2 = Ks[(ty * 4 + 2) * 64 + c];
            float a3 = Ks[(ty * 4 + 3) * 64 + c];
            float4 b = *(const float4*)&Qst[c * 64 + tx * 4];
            s[0][0] += a0 * b.x; s[0][1] += a0 * b.y; s[0][2] += a0 * b.z; s[0][3] += a0 * b.w;
            s[1][0] += a1 * b.x; s[1][1] += a1 * b.y; s[1][2] += a1 * b.z; s[1][3] += a1 * b.w;
            s[2][0] += a2 * b.x; s[2][1] += a2 * b.y; s[2][2] += a2 * b.z; s[2][3] += a2 * b.w;
            s[3][0] += a3 * b.x; s[3][1] += a3 * b.y; s[3][2] += a3 * b.z; s[3][3] += a3 * b.w;
        }

        // scale by 1/sqrt(64), relu, store Ss[kk][q]
        #pragma unroll
        for (int i = 0; i < 4; i++) {
            float4 o;
            o.x = fmaxf(s[i][0] * 0.125f, 0.f);
            o.y = fmaxf(s[i][1] * 0.125f, 0.f);
            o.z = fmaxf(s[i][2] * 0.125f, 0.f);
            o.w = fmaxf(s[i][3] * 0.125f, 0.f);
            *(float4*)&Ss[(ty * 4 + i) * 64 + tx * 4] = o;
        }
        __syncthreads();

        // acc[q][d] += sum_kk Ss[kk][q] * Vs[kk][d]
        #pragma unroll 8
        for (int kk2 = 0; kk2 < 64; kk2++) {
            float4 a = *(const float4*)&Ss[kk2 * 64 + ty * 4];
            float4 b = *(const float4*)&Vs[kk2 * 64 + tx * 4];
            acc[0][0] += a.x * b.x; acc[0][1] += a.x * b.y; acc[0][2] += a.x * b.z; acc[0][3] += a.x * b.w;
            acc[1][0] += a.y * b.x; acc[1][1] += a.y * b.y; acc[1][2] += a.y * b.z; acc[1][3] += a.y * b.w;
            acc[2][0] += a.z * b.x; acc[2][1] += a.z * b.y; acc[2][2] += a.z * b.z; acc[2][3] += a.z * b.w;
            acc[3][0] += a.w * b.x; acc[3][1] += a.w * b.y; acc[3][2] += a.w * b.z; acc[3][3] += a.w * b.w;
        }

        // row-sum (denominator) accumulation; threads 0..63, one q each
        if (tid < 64) {
            float dsum = 0.f;
            #pragma unroll 8
            for (int kk2 = 0; kk2 < 64; kk2++) dsum += Ss[kk2 * 64 + tid];
            denom[tid] += dsum;
        }
    }
    __syncthreads();

    // Normalize and write ctx in (t,b,n,D) layout (head h occupies cols [h*64, h*64+64))
    #pragma unroll
    for (int i = 0; i < 4; i++) {
        const float inv = 1.f / (denom[ty * 4 + i] + EPSV);
        float4 o;
        o.x = acc[i][0] * inv;
        o.y = acc[i][1] * inv;
        o.z = acc[i][2] * inv;
        o.w = acc[i][3] * inv;
        *(float4*)&ctx[(rowbase + qt * 64 + ty * 4 + i) * DD + col0 + tx * 4] = o;
    }
}

// ---------------------------------------------------------------------------
extern "C" void kernel_launch(void* const* d_in, const int* in_sizes, int n_in,
                              void* d_out, int out_size)
{
    (void)in_sizes; (void)n_in; (void)out_size;
    const float* x  = (const float*)d_in[0];
    const float* wq = (const float*)d_in[1];
    const float* bq = (const float*)d_in[2];
    const float* wk = (const float*)d_in[3];
    const float* bk = (const float*)d_in[4];
    const float* wv = (const float*)d_in[5];
    const float* bv = (const float*)d_in[6];
    const float* wo = (const float*)d_in[7];
    const float* bo = (const float*)d_in[8];
    float* out = (float*)d_out;

    void *pq, *pk, *pv, *pc;
    cudaGetSymbolAddress(&pq, g_q);
    cudaGetSymbolAddress(&pk, g_k);
    cudaGetSymbolAddress(&pv, g_v);
    cudaGetSymbolAddress(&pc, g_ctx);
    float* q   = (float*)pq;
    float* k   = (float*)pk;
    float* v   = (float*)pv;
    float* ctx = (float*)pc;

    cudaFuncSetAttribute(attn_kernel, cudaFuncAttributeMaxDynamicSharedMemorySize, ATTN_SMEM);

    const dim3 ggrid(DD / 128, MM / 128);  // (4, 128)
    gemm_bias_kernel<<<ggrid, 256>>>(x, wq, bq, q);
    gemm_bias_kernel<<<ggrid, 256>>>(x, wk, bk, k);
    gemm_bias_kernel<<<ggrid, 256>>>(x, wv, bv, v);
    attn_kernel<<<dim3(16, HH, TT * BB), 256, ATTN_SMEM>>>(q, k, v, ctx);
    gemm_bias_kernel<<<ggrid, 256>>>(ctx, wo, bo, out);
}

// round 3
// speedup vs baseline: 1.3215x; 1.3215x over previous
#include <cuda_runtime.h>
#include <cuda_bf16.h>
#include <cstdint>

#define TT 4
#define BB 4
#define NN 1024
#define DD 512
#define HH 8
#define HDIM 64
#define MM (TT*BB*NN)   // 16384 total rows
#define EPSV 1e-6f

// ---------------- scratch (device globals: allocation-free rule) ----------------
__device__ float g_q[MM * DD];
__device__ float g_k[MM * DD];
__device__ float g_v[MM * DD];
__device__ __nv_bfloat16 g_xhi[MM * DD];
__device__ __nv_bfloat16 g_xlo[MM * DD];
__device__ __nv_bfloat16 g_ctxhi[MM * DD];
__device__ __nv_bfloat16 g_ctxlo[MM * DD];
__device__ __nv_bfloat16 g_whi[4 * DD * DD];
__device__ __nv_bfloat16 g_wlo[4 * DD * DD];

// ---------------- PTX helpers (base ISA only: ldmatrix + mma.sync) ----------------
__device__ __forceinline__ uint32_t smem_u32(const void* p) {
    uint32_t a;
    asm("{ .reg .u64 t; cvta.to.shared.u64 t, %1; cvt.u32.u64 %0, t; }" : "=r"(a) : "l"(p));
    return a;
}
__device__ __forceinline__ void ldsm_x4(uint32_t& r0, uint32_t& r1, uint32_t& r2, uint32_t& r3,
                                        uint32_t addr) {
    asm volatile("ldmatrix.sync.aligned.m8n8.x4.shared.b16 {%0,%1,%2,%3}, [%4];"
                 : "=r"(r0), "=r"(r1), "=r"(r2), "=r"(r3) : "r"(addr));
}
__device__ __forceinline__ void mma_bf16(float& c0, float& c1, float& c2, float& c3,
                                         uint32_t a0, uint32_t a1, uint32_t a2, uint32_t a3,
                                         uint32_t b0, uint32_t b1) {
    asm volatile(
        "mma.sync.aligned.m16n8k16.row.col.f32.bf16.bf16.f32 "
        "{%0,%1,%2,%3}, {%4,%5,%6,%7}, {%8,%9}, {%0,%1,%2,%3};"
        : "+f"(c0), "+f"(c1), "+f"(c2), "+f"(c3)
        : "r"(a0), "r"(a1), "r"(a2), "r"(a3), "r"(b0), "r"(b1));
}

// ---------------- fp32 -> bf16 hi/lo split ----------------
__global__ __launch_bounds__(256) void convert_split_kernel(
    const float4* __restrict__ src,
    __nv_bfloat162* __restrict__ hi, __nv_bfloat162* __restrict__ lo, int n4)
{
    int i = blockIdx.x * blockDim.x + threadIdx.x;
    if (i >= n4) return;
    float4 v = src[i];
    __nv_bfloat16 h0 = __float2bfloat16(v.x);
    __nv_bfloat16 h1 = __float2bfloat16(v.y);
    __nv_bfloat16 h2 = __float2bfloat16(v.z);
    __nv_bfloat16 h3 = __float2bfloat16(v.w);
    __nv_bfloat162 ph0; ph0.x = h0; ph0.y = h1;
    __nv_bfloat162 ph1; ph1.x = h2; ph1.y = h3;
    __nv_bfloat162 pl0, pl1;
    pl0.x = __float2bfloat16(v.x - __bfloat162float(h0));
    pl0.y = __float2bfloat16(v.y - __bfloat162float(h1));
    pl1.x = __float2bfloat16(v.z - __bfloat162float(h2));
    pl1.y = __float2bfloat16(v.w - __bfloat162float(h3));
    hi[2 * i]     = ph0;
    hi[2 * i + 1] = ph1;
    lo[2 * i]     = pl0;
    lo[2 * i + 1] = pl1;
}

// ---------------------------------------------------------------------------
// mma.sync GEMM: C[M,512] = A[M,512] @ W[512,512]^T + bias, bf16 3-split.
// CTA 128x128, 8 warps (2x4), warp tile 64x32, BK=32.
// smem rows padded to 80B -> conflict-free ldmatrix.
// ---------------------------------------------------------------------------
#define TSTRIDE 80
#define TILE_B  (128 * TSTRIDE)    // 10240 bytes per tile

__global__ __launch_bounds__(256) void gemm_mma_kernel(
    const __nv_bfloat16* __restrict__ Ahi, const __nv_bfloat16* __restrict__ Alo,
    const __nv_bfloat16* __restrict__ Bhi, const __nv_bfloat16* __restrict__ Blo,
    const float* __restrict__ bias, float* __restrict__ C)
{
    __shared__ __align__(128) char smem[4 * TILE_B];
    const uint32_t sb = smem_u32(smem);
    const uint32_t sAh = sb;
    const uint32_t sAl = sb + TILE_B;
    const uint32_t sBh = sb + 2 * TILE_B;
    const uint32_t sBl = sb + 3 * TILE_B;

    const int tid = threadIdx.x;
    const int wid = tid >> 5;
    const int lane = tid & 31;
    const int warp_m = wid & 1;        // 0..1 -> rows 64*warp_m
    const int warp_n = wid >> 1;       // 0..3 -> cols 32*warp_n
    const int m0 = blockIdx.y * 128;
    const int n0 = blockIdx.x * 128;

    const uint4* gAh = (const uint4*)Ahi;
    const uint4* gAl = (const uint4*)Alo;
    const uint4* gBh = (const uint4*)Bhi;
    const uint4* gBl = (const uint4*)Blo;

    float acc[4][4][4];
    #pragma unroll
    for (int i = 0; i < 4; i++)
        #pragma unroll
        for (int j = 0; j < 4; j++)
            #pragma unroll
            for (int r = 0; r < 4; r++)
                acc[i][j][r] = 0.f;

    // ldmatrix lane address components (within a tile)
    const uint32_t a_lrow = (uint32_t)(lane & 15);
    const uint32_t a_lcol = (uint32_t)((lane >> 4) * 16);
    const uint32_t b_lrow = (uint32_t)(((lane >> 4) & 1) * 8 + (lane & 7));
    const uint32_t b_lcol = (uint32_t)(((lane >> 3) & 1) * 16);

    for (int c = 0; c < 16; c++) {
        __syncthreads();
        const int kq = c * 4;                   // uint4 offset within 64-uint4 row
        #pragma unroll
        for (int half = 0; half < 2; half++) {
            const int e   = half * 256 + tid;   // 0..511
            const int row = e >> 2;
            const int q   = e & 3;
            const uint32_t so = (uint32_t)(row * TSTRIDE + q * 16);
            const size_t ga = (size_t)(m0 + row) * 64 + kq + q;
            const size_t gb = (size_t)(n0 + row) * 64 + kq + q;
            *(uint4*)(smem + so)              = gAh[ga];
            *(uint4*)(smem + TILE_B + so)     = gAl[ga];
            *(uint4*)(smem + 2 * TILE_B + so) = gBh[gb];
            *(uint4*)(smem + 3 * TILE_B + so) = gBl[gb];
        }
        __syncthreads();

        #pragma unroll
        for (int ks = 0; ks < 2; ks++) {
            const uint32_t kb = (uint32_t)(ks * 32);

            // B fragments: 4 n-tiles of 8, via 2 ldmatrix.x4 per split
            uint32_t bh[4][2], bl[4][2];
            #pragma unroll
            for (int p = 0; p < 2; p++) {
                const uint32_t boff =
                    (uint32_t)(warp_n * 32 + p * 16 + b_lrow) * TSTRIDE + b_lcol + kb;
                ldsm_x4(bh[2*p][0], bh[2*p][1], bh[2*p+1][0], bh[2*p+1][1], sBh + boff);
                ldsm_x4(bl[2*p][0], bl[2*p][1], bl[2*p+1][0], bl[2*p+1][1], sBl + boff);
            }

            #pragma unroll
            for (int mt = 0; mt < 4; mt++) {
                const uint32_t aoff =
                    (uint32_t)(warp_m * 64 + mt * 16 + a_lrow) * TSTRIDE + a_lcol + kb;
                uint32_t ah0, ah1, ah2, ah3, al0, al1, al2, al3;
                ldsm_x4(ah0, ah1, ah2, ah3, sAh + aoff);
                ldsm_x4(al0, al1, al2, al3, sAl + aoff);
                #pragma unroll
                for (int nt = 0; nt < 4; nt++) {
                    mma_bf16(acc[mt][nt][0], acc[mt][nt][1], acc[mt][nt][2], acc[mt][nt][3],
                             ah0, ah1, ah2, ah3, bh[nt][0], bh[nt][1]);
                    mma_bf16(acc[mt][nt][0], acc[mt][nt][1], acc[mt][nt][2], acc[mt][nt][3],
                             ah0, ah1, ah2, ah3, bl[nt][0], bl[nt][1]);
                    mma_bf16(acc[mt][nt][0], acc[mt][nt][1], acc[mt][nt][2], acc[mt][nt][3],
                             al0, al1, al2, al3, bh[nt][0], bh[nt][1]);
                }
            }
        }
    }

    // epilogue: c0,c1 -> (row, col..col+1); c2,c3 -> (row+8, ...)
    const int rbase = m0 + warp_m * 64 + (lane >> 2);
    const int cbase = n0 + warp_n * 32 + (lane & 3) * 2;
    #pragma unroll
    for (int mt = 0; mt < 4; mt++) {
        #pragma unroll
        for (int nt = 0; nt < 4; nt++) {
            const int col = cbase + nt * 8;
            const float b0 = bias[col];
            const float b1 = bias[col + 1];
            const int r0 = rbase + mt * 16;
            float2 o0 = make_float2(acc[mt][nt][0] + b0, acc[mt][nt][1] + b1);
            float2 o1 = make_float2(acc[mt][nt][2] + b0, acc[mt][nt][3] + b1);
            *(float2*)&C[(size_t)r0 * DD + col]       = o0;
            *(float2*)&C[(size_t)(r0 + 8) * DD + col] = o1;
        }
    }
}

// ---------------------------------------------------------------------------
// Fused relu-normalized attention; writes ctx as bf16 hi/lo for final GEMM.
// ---------------------------------------------------------------------------
#define ATTN_SMEM ((4 * 64 * 64 + 64) * 4)

__global__ __launch_bounds__(256) void attn_kernel(
    const float* __restrict__ qg, const float* __restrict__ kg,
    const float* __restrict__ vg,
    __nv_bfloat16* __restrict__ ctxhi, __nv_bfloat16* __restrict__ ctxlo)
{
    extern __shared__ float smf[];
    float* Qst   = smf;
    float* Ks    = smf + 64 * 64;
    float* Vs    = smf + 2 * 64 * 64;
    float* Ss    = smf + 3 * 64 * 64;
    float* denom = smf + 4 * 64 * 64;

    const int tid = threadIdx.x;
    const int tx = tid & 15;
    const int ty = tid >> 4;
    const int qt = blockIdx.x;
    const int h  = blockIdx.y;
    const int tb = blockIdx.z;
    const size_t rowbase = (size_t)tb * NN;
    const int col0 = h * HDIM;

    {
        const int r  = tid >> 4;
        const int c4 = (tid & 15) * 4;
        #pragma unroll
        for (int rr = 0; rr < 64; rr += 16) {
            const int qq = rr + r;
            float4 t = *(const float4*)&qg[(rowbase + qt * 64 + qq) * DD + col0 + c4];
            Qst[(c4 + 0) * 64 + qq] = t.x;
            Qst[(c4 + 1) * 64 + qq] = t.y;
            Qst[(c4 + 2) * 64 + qq] = t.z;
            Qst[(c4 + 3) * 64 + qq] = t.w;
        }
    }
    if (tid < 64) denom[tid] = 0.f;

    float acc[4][4];
    #pragma unroll
    for (int i = 0; i < 4; i++)
        #pragma unroll
        for (int j = 0; j < 4; j++)
            acc[i][j] = 0.f;

    for (int kt = 0; kt < 16; kt++) {
        __syncthreads();
        {
            const int r  = tid >> 4;
            const int c4 = (tid & 15) * 4;
            #pragma unroll
            for (int rr = 0; rr < 64; rr += 16) {
                const int kkr = rr + r;
                float4 tk = *(const float4*)&kg[(rowbase + kt * 64 + kkr) * DD + col0 + c4];
                float4 tv = *(const float4*)&vg[(rowbase + kt * 64 + kkr) * DD + col0 + c4];
                *(float4*)&Ks[kkr * 64 + c4] = tk;
                *(float4*)&Vs[kkr * 64 + c4] = tv;
            }
        }
        __syncthreads();

        float s[4][4];
        #pragma unroll
        for (int i = 0; i < 4; i++)
            #pragma unroll
            for (int j = 0; j < 4; j++)
                s[i][j] = 0.f;

        #pragma unroll 8
        for (int cc = 0; cc < 64; cc++) {
            float a0 = Ks[(ty * 4 + 0) * 64 + cc];
            float a1 = Ks[(ty * 4 + 1) * 64 + cc];
            float a2 = Ks[(ty * 4 + 2) * 64 + cc];
            float a3 = Ks[(ty * 4 + 3) * 64 + cc];
            float4 b = *(const float4*)&Qst[cc * 64 + tx * 4];
            s[0][0] += a0 * b.x; s[0][1] += a0 * b.y; s[0][2] += a0 * b.z; s[0][3] += a0 * b.w;
            s[1][0] += a1 * b.x; s[1][1] += a1 * b.y; s[1][2] += a1 * b.z; s[1][3] += a1 * b.w;
            s[2][0] += a2 * b.x; s[2][1] += a2 * b.y; s[2][2] += a2 * b.z; s[2][3] += a2 * b.w;
            s[3][0] += a3 * b.x; s[3][1] += a3 * b.y; s[3][2] += a3 * b.z; s[3][3] += a3 * b.w;
        }

        #pragma unroll
        for (int i = 0; i < 4; i++) {
            float4 o;
            o.x = fmaxf(s[i][0] * 0.125f, 0.f);
            o.y = fmaxf(s[i][1] * 0.125f, 0.f);
            o.z = fmaxf(s[i][2] * 0.125f, 0.f);
            o.w = fmaxf(s[i][3] * 0.125f, 0.f);
            *(float4*)&Ss[(ty * 4 + i) * 64 + tx * 4] = o;
        }
        __syncthreads();

        #pragma unroll 8
        for (int kk2 = 0; kk2 < 64; kk2++) {
            float4 a = *(const float4*)&Ss[kk2 * 64 + ty * 4];
            float4 b = *(const float4*)&Vs[kk2 * 64 + tx * 4];
            acc[0][0] += a.x * b.x; acc[0][1] += a.x * b.y; acc[0][2] += a.x * b.z; acc[0][3] += a.x * b.w;
            acc[1][0] += a.y * b.x; acc[1][1] += a.y * b.y; acc[1][2] += a.y * b.z; acc[1][3] += a.y * b.w;
            acc[2][0] += a.z * b.x; acc[2][1] += a.z * b.y; acc[2][2] += a.z * b.z; acc[2][3] += a.z * b.w;
            acc[3][0] += a.w * b.x; acc[3][1] += a.w * b.y; acc[3][2] += a.w * b.z; acc[3][3] += a.w * b.w;
        }

        if (tid < 64) {
            float dsum = 0.f;
            #pragma unroll 8
            for (int kk2 = 0; kk2 < 64; kk2++) dsum += Ss[kk2 * 64 + tid];
            denom[tid] += dsum;
        }
    }
    __syncthreads();

    #pragma unroll
    for (int i = 0; i < 4; i++) {
        const float inv = 1.f / (denom[ty * 4 + i] + EPSV);
        float o0 = acc[i][0] * inv;
        float o1 = acc[i][1] * inv;
        float o2 = acc[i][2] * inv;
        float o3 = acc[i][3] * inv;
        __nv_bfloat16 h0 = __float2bfloat16(o0);
        __nv_bfloat16 h1 = __float2bfloat16(o1);
        __nv_bfloat16 h2 = __float2bfloat16(o2);
        __nv_bfloat16 h3 = __float2bfloat16(o3);
        __nv_bfloat162 ph0; ph0.x = h0; ph0.y = h1;
        __nv_bfloat162 ph1; ph1.x = h2; ph1.y = h3;
        __nv_bfloat162 pl0, pl1;
        pl0.x = __float2bfloat16(o0 - __bfloat162float(h0));
        pl0.y = __float2bfloat16(o1 - __bfloat162float(h1));
        pl1.x = __float2bfloat16(o2 - __bfloat162float(h2));
        pl1.y = __float2bfloat16(o3 - __bfloat162float(h3));
        const size_t base = (rowbase + qt * 64 + ty * 4 + i) * DD + col0 + tx * 4;
        *(__nv_bfloat162*)&ctxhi[base]     = ph0;
        *(__nv_bfloat162*)&ctxhi[base + 2] = ph1;
        *(__nv_bfloat162*)&ctxlo[base]     = pl0;
        *(__nv_bfloat162*)&ctxlo[base + 2] = pl1;
    }
}

// ---------------------------------------------------------------------------
extern "C" void kernel_launch(void* const* d_in, const int* in_sizes, int n_in,
                              void* d_out, int out_size)
{
    (void)in_sizes; (void)n_in; (void)out_size;
    const float* x  = (const float*)d_in[0];
    const float* wq = (const float*)d_in[1];
    const float* bq = (const float*)d_in[2];
    const float* wk = (const float*)d_in[3];
    const float* bk = (const float*)d_in[4];
    const float* wv = (const float*)d_in[5];
    const float* bv = (const float*)d_in[6];
    const float* wo = (const float*)d_in[7];
    const float* bo = (const float*)d_in[8];
    float* out = (float*)d_out;

    void *pq, *pk, *pv, *pxh, *pxl, *pch, *pcl, *pwh, *pwl;
    cudaGetSymbolAddress(&pq,  g_q);
    cudaGetSymbolAddress(&pk,  g_k);
    cudaGetSymbolAddress(&pv,  g_v);
    cudaGetSymbolAddress(&pxh, g_xhi);
    cudaGetSymbolAddress(&pxl, g_xlo);
    cudaGetSymbolAddress(&pch, g_ctxhi);
    cudaGetSymbolAddress(&pcl, g_ctxlo);
    cudaGetSymbolAddress(&pwh, g_whi);
    cudaGetSymbolAddress(&pwl, g_wlo);
    float* q = (float*)pq;
    float* k = (float*)pk;
    float* v = (float*)pv;
    __nv_bfloat16* xhi = (__nv_bfloat16*)pxh;
    __nv_bfloat16* xlo = (__nv_bfloat16*)pxl;
    __nv_bfloat16* chi = (__nv_bfloat16*)pch;
    __nv_bfloat16* clo = (__nv_bfloat16*)pcl;
    __nv_bfloat16* whi = (__nv_bfloat16*)pwh;
    __nv_bfloat16* wlo = (__nv_bfloat16*)pwl;

    cudaFuncSetAttribute(attn_kernel, cudaFuncAttributeMaxDynamicSharedMemorySize, ATTN_SMEM);

    // fp32 -> bf16 hi/lo splits
    {
        const int n4x = MM * DD / 4;
        convert_split_kernel<<<(n4x + 255) / 256, 256>>>(
            (const float4*)x, (__nv_bfloat162*)xhi, (__nv_bfloat162*)xlo, n4x);
        const int n4w = DD * DD / 4;
        const float* ws[4] = {wq, wk, wv, wo};
        for (int i = 0; i < 4; i++) {
            convert_split_kernel<<<(n4w + 255) / 256, 256>>>(
                (const float4*)ws[i],
                (__nv_bfloat162*)(whi + (size_t)i * DD * DD),
                (__nv_bfloat162*)(wlo + (size_t)i * DD * DD), n4w);
        }
    }

    const dim3 ggrid(DD / 128, MM / 128);   // (4, 128)
    gemm_mma_kernel<<<ggrid, 256>>>(xhi, xlo, whi, wlo, bq, q);
    gemm_mma_kernel<<<ggrid, 256>>>(xhi, xlo, whi + (size_t)1 * DD * DD, wlo + (size_t)1 * DD * DD, bk, k);
    gemm_mma_kernel<<<ggrid, 256>>>(xhi, xlo, whi + (size_t)2 * DD * DD, wlo + (size_t)2 * DD * DD, bv, v);

    attn_kernel<<<dim3(16, HH, TT * BB), 256, ATTN_SMEM>>>(q, k, v, chi, clo);

    gemm_mma_kernel<<<ggrid, 256>>>(chi, clo, whi + (size_t)3 * DD * DD, wlo + (size_t)3 * DD * DD, bo, out);
}

// round 4
// speedup vs baseline: 2.0257x; 1.5329x over previous
#include <cuda_runtime.h>
#include <cuda_bf16.h>
#include <cstdint>

#define TT 4
#define BB 4
#define NN 1024
#define DD 512
#define HH 8
#define HDIM 64
#define MM (TT*BB*NN)   // 16384 total rows
#define EPSV 1e-6f

// ---------------- scratch (device globals: allocation-free rule) ----------------
__device__ __nv_bfloat16 g_qhi[MM * DD];
__device__ __nv_bfloat16 g_qlo[MM * DD];
__device__ __nv_bfloat16 g_khi[MM * DD];
__device__ __nv_bfloat16 g_klo[MM * DD];
__device__ __nv_bfloat16 g_vhi[MM * DD];
__device__ __nv_bfloat16 g_vlo[MM * DD];
__device__ __nv_bfloat16 g_xhi[MM * DD];
__device__ __nv_bfloat16 g_xlo[MM * DD];
__device__ __nv_bfloat16 g_ctxhi[MM * DD];
__device__ __nv_bfloat16 g_ctxlo[MM * DD];
__device__ __nv_bfloat16 g_whi[4 * DD * DD];
__device__ __nv_bfloat16 g_wlo[4 * DD * DD];

// ---------------- PTX helpers (base ISA: ldmatrix + mma.sync) ----------------
__device__ __forceinline__ uint32_t smem_u32(const void* p) {
    uint32_t a;
    asm("{ .reg .u64 t; cvta.to.shared.u64 t, %1; cvt.u32.u64 %0, t; }" : "=r"(a) : "l"(p));
    return a;
}
__device__ __forceinline__ void ldsm_x4(uint32_t& r0, uint32_t& r1, uint32_t& r2, uint32_t& r3,
                                        uint32_t addr) {
    asm volatile("ldmatrix.sync.aligned.m8n8.x4.shared.b16 {%0,%1,%2,%3}, [%4];"
                 : "=r"(r0), "=r"(r1), "=r"(r2), "=r"(r3) : "r"(addr));
}
__device__ __forceinline__ void mma_bf16(float& c0, float& c1, float& c2, float& c3,
                                         uint32_t a0, uint32_t a1, uint32_t a2, uint32_t a3,
                                         uint32_t b0, uint32_t b1) {
    asm volatile(
        "mma.sync.aligned.m16n8k16.row.col.f32.bf16.bf16.f32 "
        "{%0,%1,%2,%3}, {%4,%5,%6,%7}, {%8,%9}, {%0,%1,%2,%3};"
        : "+f"(c0), "+f"(c1), "+f"(c2), "+f"(c3)
        : "r"(a0), "r"(a1), "r"(a2), "r"(a3), "r"(b0), "r"(b1));
}
__device__ __forceinline__ void mma4(float* c, const uint32_t* a, uint32_t b0, uint32_t b1) {
    mma_bf16(c[0], c[1], c[2], c[3], a[0], a[1], a[2], a[3], b0, b1);
}
__device__ __forceinline__ void pack_split(float x, float y, uint32_t& hi, uint32_t& lo) {
    __nv_bfloat16 hx = __float2bfloat16(x), hy = __float2bfloat16(y);
    __nv_bfloat162 ph; ph.x = hx; ph.y = hy;
    __nv_bfloat162 pl;
    pl.x = __float2bfloat16(x - __bfloat162float(hx));
    pl.y = __float2bfloat16(y - __bfloat162float(hy));
    hi = *(uint32_t*)&ph;
    lo = *(uint32_t*)&pl;
}

// ---------------- fp32 -> bf16 hi/lo split ----------------
__global__ __launch_bounds__(256) void convert_split_kernel(
    const float4* __restrict__ src,
    __nv_bfloat162* __restrict__ hi, __nv_bfloat162* __restrict__ lo, int n4)
{
    int i = blockIdx.x * blockDim.x + threadIdx.x;
    if (i >= n4) return;
    float4 v = src[i];
    uint32_t h0, l0, h1, l1;
    pack_split(v.x, v.y, h0, l0);
    pack_split(v.z, v.w, h1, l1);
    hi[2 * i]     = *(__nv_bfloat162*)&h0;
    hi[2 * i + 1] = *(__nv_bfloat162*)&h1;
    lo[2 * i]     = *(__nv_bfloat162*)&l0;
    lo[2 * i + 1] = *(__nv_bfloat162*)&l1;
}

// ---------------------------------------------------------------------------
// mma.sync GEMM: C[M,512] = A[M,512] @ W[512,512]^T + bias, bf16 3-split.
// CTA 128x128, 8 warps (2x4), warp tile 64x32, BK=32.
// MODE 0: fp32 output.  MODE 1: bf16 hi/lo split output.
// ---------------------------------------------------------------------------
#define TSTRIDE 80
#define TILE_B  (128 * TSTRIDE)

template<int MODE>
__global__ __launch_bounds__(256) void gemm_mma_kernel(
    const __nv_bfloat16* __restrict__ Ahi, const __nv_bfloat16* __restrict__ Alo,
    const __nv_bfloat16* __restrict__ Bhi, const __nv_bfloat16* __restrict__ Blo,
    const float* __restrict__ bias, float* __restrict__ C,
    __nv_bfloat16* __restrict__ Chi, __nv_bfloat16* __restrict__ Clo)
{
    __shared__ __align__(128) char smem[4 * TILE_B];
    const uint32_t sb = smem_u32(smem);
    const uint32_t sAh = sb;
    const uint32_t sAl = sb + TILE_B;
    const uint32_t sBh = sb + 2 * TILE_B;
    const uint32_t sBl = sb + 3 * TILE_B;

    const int tid = threadIdx.x;
    const int wid = tid >> 5;
    const int lane = tid & 31;
    const int warp_m = wid & 1;
    const int warp_n = wid >> 1;
    const int m0 = blockIdx.y * 128;
    const int n0 = blockIdx.x * 128;

    const uint4* gAh = (const uint4*)Ahi;
    const uint4* gAl = (const uint4*)Alo;
    const uint4* gBh = (const uint4*)Bhi;
    const uint4* gBl = (const uint4*)Blo;

    float acc[4][4][4];
    #pragma unroll
    for (int i = 0; i < 4; i++)
        #pragma unroll
        for (int j = 0; j < 4; j++)
            #pragma unroll
            for (int r = 0; r < 4; r++)
                acc[i][j][r] = 0.f;

    const uint32_t a_lrow = (uint32_t)(lane & 15);
    const uint32_t a_lcol = (uint32_t)((lane >> 4) * 16);
    const uint32_t b_lrow = (uint32_t)(((lane >> 4) & 1) * 8 + (lane & 7));
    const uint32_t b_lcol = (uint32_t)(((lane >> 3) & 1) * 16);

    for (int c = 0; c < 16; c++) {
        __syncthreads();
        const int kq = c * 4;
        #pragma unroll
        for (int half = 0; half < 2; half++) {
            const int e   = half * 256 + tid;
            const int row = e >> 2;
            const int q   = e & 3;
            const uint32_t so = (uint32_t)(row * TSTRIDE + q * 16);
            const size_t ga = (size_t)(m0 + row) * 64 + kq + q;
            const size_t gb = (size_t)(n0 + row) * 64 + kq + q;
            *(uint4*)(smem + so)              = gAh[ga];
            *(uint4*)(smem + TILE_B + so)     = gAl[ga];
            *(uint4*)(smem + 2 * TILE_B + so) = gBh[gb];
            *(uint4*)(smem + 3 * TILE_B + so) = gBl[gb];
        }
        __syncthreads();

        #pragma unroll
        for (int ks = 0; ks < 2; ks++) {
            const uint32_t kb = (uint32_t)(ks * 32);
            uint32_t bh[4][2], bl[4][2];
            #pragma unroll
            for (int p = 0; p < 2; p++) {
                const uint32_t boff =
                    (uint32_t)(warp_n * 32 + p * 16 + b_lrow) * TSTRIDE + b_lcol + kb;
                ldsm_x4(bh[2*p][0], bh[2*p][1], bh[2*p+1][0], bh[2*p+1][1], sBh + boff);
                ldsm_x4(bl[2*p][0], bl[2*p][1], bl[2*p+1][0], bl[2*p+1][1], sBl + boff);
            }
            #pragma unroll
            for (int mt = 0; mt < 4; mt++) {
                const uint32_t aoff =
                    (uint32_t)(warp_m * 64 + mt * 16 + a_lrow) * TSTRIDE + a_lcol + kb;
                uint32_t ah0, ah1, ah2, ah3, al0, al1, al2, al3;
                ldsm_x4(ah0, ah1, ah2, ah3, sAh + aoff);
                ldsm_x4(al0, al1, al2, al3, sAl + aoff);
                #pragma unroll
                for (int nt = 0; nt < 4; nt++) {
                    mma_bf16(acc[mt][nt][0], acc[mt][nt][1], acc[mt][nt][2], acc[mt][nt][3],
                             ah0, ah1, ah2, ah3, bh[nt][0], bh[nt][1]);
                    mma_bf16(acc[mt][nt][0], acc[mt][nt][1], acc[mt][nt][2], acc[mt][nt][3],
                             ah0, ah1, ah2, ah3, bl[nt][0], bl[nt][1]);
                    mma_bf16(acc[mt][nt][0], acc[mt][nt][1], acc[mt][nt][2], acc[mt][nt][3],
                             al0, al1, al2, al3, bh[nt][0], bh[nt][1]);
                }
            }
        }
    }

    const int rbase = m0 + warp_m * 64 + (lane >> 2);
    const int cbase = n0 + warp_n * 32 + (lane & 3) * 2;
    #pragma unroll
    for (int mt = 0; mt < 4; mt++) {
        #pragma unroll
        for (int nt = 0; nt < 4; nt++) {
            const int col = cbase + nt * 8;
            const float b0 = bias[col];
            const float b1 = bias[col + 1];
            const int r0 = rbase + mt * 16;
            const float o00 = acc[mt][nt][0] + b0, o01 = acc[mt][nt][1] + b1;
            const float o10 = acc[mt][nt][2] + b0, o11 = acc[mt][nt][3] + b1;
            if (MODE == 0) {
                *(float2*)&C[(size_t)r0 * DD + col]       = make_float2(o00, o01);
                *(float2*)&C[(size_t)(r0 + 8) * DD + col] = make_float2(o10, o11);
            } else {
                uint32_t h0, l0, h1, l1;
                pack_split(o00, o01, h0, l0);
                pack_split(o10, o11, h1, l1);
                *(uint32_t*)&Chi[(size_t)r0 * DD + col]       = h0;
                *(uint32_t*)&Clo[(size_t)r0 * DD + col]       = l0;
                *(uint32_t*)&Chi[(size_t)(r0 + 8) * DD + col] = h1;
                *(uint32_t*)&Clo[(size_t)(r0 + 8) * DD + col] = l1;
            }
        }
    }
}

// ---------------------------------------------------------------------------
// Tensor-core fused relu-normalized attention.
// Block: 128 q-rows x 1 head x 1 (t,b); 8 warps, each 16 q-rows.
// K/V stream in 64-row tiles; V transposed into smem at load.
// All GEMMs bf16 3-split with fp32 accumulate.
// ---------------------------------------------------------------------------
#define ASTRIDE 144
#define OQLO  18432            // 128*144
#define OKHI  36864
#define OKLO  46080            // +64*144
#define OVHI  55296
#define OVLO  64512
#define ATTN_SMEM 73728

__global__ __launch_bounds__(256) void attn_mma_kernel(
    const __nv_bfloat16* __restrict__ qhi, const __nv_bfloat16* __restrict__ qlo,
    const __nv_bfloat16* __restrict__ khi, const __nv_bfloat16* __restrict__ klo,
    const __nv_bfloat16* __restrict__ vhi, const __nv_bfloat16* __restrict__ vlo,
    __nv_bfloat16* __restrict__ ctxhi, __nv_bfloat16* __restrict__ ctxlo)
{
    extern __shared__ char smem_[];
    const uint32_t sb = smem_u32(smem_);

    const int tid = threadIdx.x;
    const int wid = tid >> 5;
    const int lane = tid & 31;
    const int qt = blockIdx.x;      // 0..7 (128-row q tiles)
    const int h  = blockIdx.y;      // 0..7
    const int tb = blockIdx.z;      // 0..15
    const size_t rowbase = (size_t)tb * NN;
    const int col0 = h * HDIM;
    const int q0 = qt * 128;
    const int cq8 = col0 >> 3;      // uint4 col offset

    const uint4* gqh = (const uint4*)qhi;
    const uint4* gql = (const uint4*)qlo;
    const uint4* gkh = (const uint4*)khi;
    const uint4* gkl = (const uint4*)klo;
    const uint4* gvh = (const uint4*)vhi;
    const uint4* gvl = (const uint4*)vlo;

    // ---- load Q tile (128 x 64 bf16, hi/lo) ----
    #pragma unroll
    for (int it = 0; it < 4; it++) {
        const int idx = it * 256 + tid;        // 0..1023
        const int r  = idx >> 3;
        const int ch = idx & 7;
        const size_t g = (rowbase + q0 + r) * 64 + cq8 + ch;
        const uint32_t so = (uint32_t)(r * ASTRIDE + ch * 16);
        *(uint4*)(smem_ + so)        = gqh[g];
        *(uint4*)(smem_ + OQLO + so) = gql[g];
    }
    __syncthreads();

    // ---- Q fragments (per warp: rows wid*16..+15, 4 k-steps of 16) ----
    const uint32_t a_lrow = (uint32_t)(lane & 15);
    const uint32_t a_lcol = (uint32_t)((lane >> 4) * 16);
    const uint32_t b_lrow = (uint32_t)(((lane >> 4) & 1) * 8 + (lane & 7));
    const uint32_t b_lcol = (uint32_t)(((lane >> 3) & 1) * 16);

    uint32_t qh[4][4], ql[4][4];
    #pragma unroll
    for (int ks = 0; ks < 4; ks++) {
        const uint32_t aoff = (uint32_t)(wid * 16 + a_lrow) * ASTRIDE + a_lcol + ks * 32;
        ldsm_x4(qh[ks][0], qh[ks][1], qh[ks][2], qh[ks][3], sb + aoff);
        ldsm_x4(ql[ks][0], ql[ks][1], ql[ks][2], ql[ks][3], sb + OQLO + aoff);
    }

    float acc[8][4];
    #pragma unroll
    for (int i = 0; i < 8; i++)
        #pragma unroll
        for (int j = 0; j < 4; j++)
            acc[i][j] = 0.f;
    float dsum0 = 0.f, dsum1 = 0.f;

    for (int kt = 0; kt < 16; kt++) {
        __syncthreads();
        // K tiles (64 x 64): natural layout
        #pragma unroll
        for (int it = 0; it < 2; it++) {
            const int idx = it * 256 + tid;     // 0..511
            const int r  = idx >> 3;
            const int ch = idx & 7;
            const size_t g = (rowbase + kt * 64 + r) * 64 + cq8 + ch;
            const uint32_t so = (uint32_t)(r * ASTRIDE + ch * 16);
            *(uint4*)(smem_ + OKHI + so) = gkh[g];
            *(uint4*)(smem_ + OKLO + so) = gkl[g];
        }
        // V tiles transposed: Vt[d][kk]
        #pragma unroll
        for (int it = 0; it < 2; it++) {
            const int idx = it * 256 + tid;
            const int kk  = idx & 63;
            const int chv = idx >> 6;           // 0..7 over both iters
            const size_t g = (rowbase + kt * 64 + kk) * 64 + cq8 + chv;
            uint4 uh = gvh[g];
            uint4 ul = gvl[g];
            const uint32_t wh[4] = {uh.x, uh.y, uh.z, uh.w};
            const uint32_t wl[4] = {ul.x, ul.y, ul.z, ul.w};
            #pragma unroll
            for (int j = 0; j < 4; j++) {
                const int d = chv * 8 + 2 * j;
                *(uint16_t*)(smem_ + OVHI + (d    ) * ASTRIDE + kk * 2) = (uint16_t)(wh[j] & 0xffff);
                *(uint16_t*)(smem_ + OVHI + (d + 1) * ASTRIDE + kk * 2) = (uint16_t)(wh[j] >> 16);
                *(uint16_t*)(smem_ + OVLO + (d    ) * ASTRIDE + kk * 2) = (uint16_t)(wl[j] & 0xffff);
                *(uint16_t*)(smem_ + OVLO + (d + 1) * ASTRIDE + kk * 2) = (uint16_t)(wl[j] >> 16);
            }
        }
        __syncthreads();

        // ---- phase 1: S = Q K^T (3-split) ----
        float s[8][4];
        #pragma unroll
        for (int i = 0; i < 8; i++)
            #pragma unroll
            for (int j = 0; j < 4; j++)
                s[i][j] = 0.f;

        #pragma unroll
        for (int ks = 0; ks < 4; ks++) {
            #pragma unroll
            for (int p = 0; p < 4; p++) {
                const uint32_t boff = (uint32_t)(p * 16 + b_lrow) * ASTRIDE + b_lcol + ks * 32;
                uint32_t kh0, kh1, kh2, kh3, kl0, kl1, kl2, kl3;
                ldsm_x4(kh0, kh1, kh2, kh3, sb + OKHI + boff);
                ldsm_x4(kl0, kl1, kl2, kl3, sb + OKLO + boff);
                mma4(s[2*p],     qh[ks], kh0, kh1);
                mma4(s[2*p],     qh[ks], kl0, kl1);
                mma4(s[2*p],     ql[ks], kh0, kh1);
                mma4(s[2*p + 1], qh[ks], kh2, kh3);
                mma4(s[2*p + 1], qh[ks], kl2, kl3);
                mma4(s[2*p + 1], ql[ks], kh2, kh3);
            }
        }

        // ---- relu/scale, denominator, repack as A fragments ----
        #pragma unroll
        for (int nt = 0; nt < 8; nt++) {
            #pragma unroll
            for (int e = 0; e < 4; e++)
                s[nt][e] = fmaxf(s[nt][e] * 0.125f, 0.f);
            dsum0 += s[nt][0] + s[nt][1];
            dsum1 += s[nt][2] + s[nt][3];
        }
        uint32_t ahi[4][4], alo[4][4];
        #pragma unroll
        for (int g = 0; g < 4; g++) {
            pack_split(s[2*g][0],     s[2*g][1],     ahi[g][0], alo[g][0]);
            pack_split(s[2*g][2],     s[2*g][3],     ahi[g][1], alo[g][1]);
            pack_split(s[2*g + 1][0], s[2*g + 1][1], ahi[g][2], alo[g][2]);
            pack_split(s[2*g + 1][2], s[2*g + 1][3], ahi[g][3], alo[g][3]);
        }

        // ---- phase 2: ctx += S V (3-split, V transposed in smem) ----
        #pragma unroll
        for (int g = 0; g < 4; g++) {
            #pragma unroll
            for (int p = 0; p < 4; p++) {
                const uint32_t boff = (uint32_t)(p * 16 + b_lrow) * ASTRIDE + b_lcol + g * 32;
                uint32_t vh0, vh1, vh2, vh3, vl0, vl1, vl2, vl3;
                ldsm_x4(vh0, vh1, vh2, vh3, sb + OVHI + boff);
                ldsm_x4(vl0, vl1, vl2, vl3, sb + OVLO + boff);
                mma4(acc[2*p],     ahi[g], vh0, vh1);
                mma4(acc[2*p],     ahi[g], vl0, vl1);
                mma4(acc[2*p],     alo[g], vh0, vh1);
                mma4(acc[2*p + 1], ahi[g], vh2, vh3);
                mma4(acc[2*p + 1], ahi[g], vl2, vl3);
                mma4(acc[2*p + 1], alo[g], vh2, vh3);
            }
        }
    }

    // ---- denominator reduce across the quad (cols), normalize, write ----
    dsum0 += __shfl_xor_sync(0xffffffffu, dsum0, 1);
    dsum0 += __shfl_xor_sync(0xffffffffu, dsum0, 2);
    dsum1 += __shfl_xor_sync(0xffffffffu, dsum1, 1);
    dsum1 += __shfl_xor_sync(0xffffffffu, dsum1, 2);
    const float inv0 = 1.f / (dsum0 + EPSV);
    const float inv1 = 1.f / (dsum1 + EPSV);

    const size_t r0 = rowbase + q0 + wid * 16 + (lane >> 2);
    const int ccol = (lane & 3) * 2;
    #pragma unroll
    for (int nt = 0; nt < 8; nt++) {
        const int col = col0 + nt * 8 + ccol;
        uint32_t h0, l0, h1, l1;
        pack_split(acc[nt][0] * inv0, acc[nt][1] * inv0, h0, l0);
        pack_split(acc[nt][2] * inv1, acc[nt][3] * inv1, h1, l1);
        *(uint32_t*)&ctxhi[r0 * DD + col]       = h0;
        *(uint32_t*)&ctxlo[r0 * DD + col]       = l0;
        *(uint32_t*)&ctxhi[(r0 + 8) * DD + col] = h1;
        *(uint32_t*)&ctxlo[(r0 + 8) * DD + col] = l1;
    }
}

// ---------------------------------------------------------------------------
extern "C" void kernel_launch(void* const* d_in, const int* in_sizes, int n_in,
                              void* d_out, int out_size)
{
    (void)in_sizes; (void)n_in; (void)out_size;
    const float* x  = (const float*)d_in[0];
    const float* wq = (const float*)d_in[1];
    const float* bq = (const float*)d_in[2];
    const float* wk = (const float*)d_in[3];
    const float* bk = (const float*)d_in[4];
    const float* wv = (const float*)d_in[5];
    const float* bv = (const float*)d_in[6];
    const float* wo = (const float*)d_in[7];
    const float* bo = (const float*)d_in[8];
    float* out = (float*)d_out;

    void *pqh, *pql, *pkh, *pkl, *pvh, *pvl, *pxh, *pxl, *pch, *pcl, *pwh, *pwl;
    cudaGetSymbolAddress(&pqh, g_qhi);
    cudaGetSymbolAddress(&pql, g_qlo);
    cudaGetSymbolAddress(&pkh, g_khi);
    cudaGetSymbolAddress(&pkl, g_klo);
    cudaGetSymbolAddress(&pvh, g_vhi);
    cudaGetSymbolAddress(&pvl, g_vlo);
    cudaGetSymbolAddress(&pxh, g_xhi);
    cudaGetSymbolAddress(&pxl, g_xlo);
    cudaGetSymbolAddress(&pch, g_ctxhi);
    cudaGetSymbolAddress(&pcl, g_ctxlo);
    cudaGetSymbolAddress(&pwh, g_whi);
    cudaGetSymbolAddress(&pwl, g_wlo);
    __nv_bfloat16* qhi = (__nv_bfloat16*)pqh;
    __nv_bfloat16* qlo = (__nv_bfloat16*)pql;
    __nv_bfloat16* khi = (__nv_bfloat16*)pkh;
    __nv_bfloat16* klo = (__nv_bfloat16*)pkl;
    __nv_bfloat16* vhi = (__nv_bfloat16*)pvh;
    __nv_bfloat16* vlo = (__nv_bfloat16*)pvl;
    __nv_bfloat16* xhi = (__nv_bfloat16*)pxh;
    __nv_bfloat16* xlo = (__nv_bfloat16*)pxl;
    __nv_bfloat16* chi = (__nv_bfloat16*)pch;
    __nv_bfloat16* clo = (__nv_bfloat16*)pcl;
    __nv_bfloat16* whi = (__nv_bfloat16*)pwh;
    __nv_bfloat16* wlo = (__nv_bfloat16*)pwl;

    cudaFuncSetAttribute(attn_mma_kernel, cudaFuncAttributeMaxDynamicSharedMemorySize, ATTN_SMEM);

    // fp32 -> bf16 hi/lo splits
    {
        const int n4x = MM * DD / 4;
        convert_split_kernel<<<(n4x + 255) / 256, 256>>>(
            (const float4*)x, (__nv_bfloat162*)xhi, (__nv_bfloat162*)xlo, n4x);
        const int n4w = DD * DD / 4;
        const float* ws[4] = {wq, wk, wv, wo};
        for (int i = 0; i < 4; i++) {
            convert_split_kernel<<<(n4w + 255) / 256, 256>>>(
                (const float4*)ws[i],
                (__nv_bfloat162*)(whi + (size_t)i * DD * DD),
                (__nv_bfloat162*)(wlo + (size_t)i * DD * DD), n4w);
        }
    }

    const dim3 ggrid(DD / 128, MM / 128);   // (4, 128)
    gemm_mma_kernel<1><<<ggrid, 256>>>(xhi, xlo, whi, wlo, bq, nullptr, qhi, qlo);
    gemm_mma_kernel<1><<<ggrid, 256>>>(xhi, xlo, whi + (size_t)1 * DD * DD, wlo + (size_t)1 * DD * DD, bk, nullptr, khi, klo);
    gemm_mma_kernel<1><<<ggrid, 256>>>(xhi, xlo, whi + (size_t)2 * DD * DD, wlo + (size_t)2 * DD * DD, bv, nullptr, vhi, vlo);

    attn_mma_kernel<<<dim3(8, HH, TT * BB), 256, ATTN_SMEM>>>(qhi, qlo, khi, klo, vhi, vlo, chi, clo);

    gemm_mma_kernel<0><<<ggrid, 256>>>(chi, clo, whi + (size_t)3 * DD * DD, wlo + (size_t)3 * DD * DD, bo, out, nullptr, nullptr);
}

// round 6
// speedup vs baseline: 2.7963x; 1.3804x over previous
#include <cuda_runtime.h>
#include <cuda_bf16.h>
#include <cstdint>

#define TT 4
#define BB 4
#define NN 1024
#define DD 512
#define HH 8
#define HDIM 64
#define MM (TT*BB*NN)   // 16384 total rows
#define EPSV 1e-6f

// ---------------- scratch (device globals: allocation-free rule) ----------------
__device__ __nv_bfloat16 g_qhi[MM * DD];
__device__ __nv_bfloat16 g_qlo[MM * DD];
__device__ __nv_bfloat16 g_khi[MM * DD];
__device__ __nv_bfloat16 g_klo[MM * DD];
__device__ __nv_bfloat16 g_vhi[MM * DD];
__device__ __nv_bfloat16 g_vlo[MM * DD];
__device__ __nv_bfloat16 g_xhi[MM * DD];
__device__ __nv_bfloat16 g_xlo[MM * DD];
__device__ __nv_bfloat16 g_ctxhi[MM * DD];
__device__ __nv_bfloat16 g_ctxlo[MM * DD];
__device__ __nv_bfloat16 g_whi[4 * DD * DD];
__device__ __nv_bfloat16 g_wlo[4 * DD * DD];

// ---------------- PTX helpers (base ISA: ldmatrix + mma.sync + cp.async) ------
__device__ __forceinline__ uint32_t smem_u32(const void* p) {
    uint32_t a;
    asm("{ .reg .u64 t; cvta.to.shared.u64 t, %1; cvt.u32.u64 %0, t; }" : "=r"(a) : "l"(p));
    return a;
}
__device__ __forceinline__ void ldsm_x4(uint32_t& r0, uint32_t& r1, uint32_t& r2, uint32_t& r3,
                                        uint32_t addr) {
    asm volatile("ldmatrix.sync.aligned.m8n8.x4.shared.b16 {%0,%1,%2,%3}, [%4];"
                 : "=r"(r0), "=r"(r1), "=r"(r2), "=r"(r3) : "r"(addr));
}
__device__ __forceinline__ void ldsm_x4_t(uint32_t& r0, uint32_t& r1, uint32_t& r2, uint32_t& r3,
                                          uint32_t addr) {
    asm volatile("ldmatrix.sync.aligned.m8n8.x4.trans.shared.b16 {%0,%1,%2,%3}, [%4];"
                 : "=r"(r0), "=r"(r1), "=r"(r2), "=r"(r3) : "r"(addr));
}
__device__ __forceinline__ void mma_bf16(float& c0, float& c1, float& c2, float& c3,
                                         uint32_t a0, uint32_t a1, uint32_t a2, uint32_t a3,
                                         uint32_t b0, uint32_t b1) {
    asm volatile(
        "mma.sync.aligned.m16n8k16.row.col.f32.bf16.bf16.f32 "
        "{%0,%1,%2,%3}, {%4,%5,%6,%7}, {%8,%9}, {%0,%1,%2,%3};"
        : "+f"(c0), "+f"(c1), "+f"(c2), "+f"(c3)
        : "r"(a0), "r"(a1), "r"(a2), "r"(a3), "r"(b0), "r"(b1));
}
__device__ __forceinline__ void mma4(float* c, const uint32_t* a, uint32_t b0, uint32_t b1) {
    mma_bf16(c[0], c[1], c[2], c[3], a[0], a[1], a[2], a[3], b0, b1);
}
__device__ __forceinline__ void cp16(uint32_t saddr, const void* g) {
    asm volatile("cp.async.cg.shared.global [%0], [%1], 16;" :: "r"(saddr), "l"(g) : "memory");
}
__device__ __forceinline__ void cp_commit() {
    asm volatile("cp.async.commit_group;" ::: "memory");
}
__device__ __forceinline__ void cp_wait1() {
    asm volatile("cp.async.wait_group 1;" ::: "memory");
}
__device__ __forceinline__ void cp_wait0() {
    asm volatile("cp.async.wait_group 0;" ::: "memory");
}
__device__ __forceinline__ void pack_split(float x, float y, uint32_t& hi, uint32_t& lo) {
    __nv_bfloat16 hx = __float2bfloat16(x), hy = __float2bfloat16(y);
    __nv_bfloat162 ph; ph.x = hx; ph.y = hy;
    __nv_bfloat162 pl;
    pl.x = __float2bfloat16(x - __bfloat162float(hx));
    pl.y = __float2bfloat16(y - __bfloat162float(hy));
    hi = *(uint32_t*)&ph;
    lo = *(uint32_t*)&pl;
}

// ---------------- fp32 -> bf16 hi/lo split ----------------
__global__ __launch_bounds__(256) void convert_split_kernel(
    const float4* __restrict__ src,
    __nv_bfloat162* __restrict__ hi, __nv_bfloat162* __restrict__ lo, int n4)
{
    int i = blockIdx.x * blockDim.x + threadIdx.x;
    if (i >= n4) return;
    float4 v = src[i];
    uint32_t h0, l0, h1, l1;
    pack_split(v.x, v.y, h0, l0);
    pack_split(v.z, v.w, h1, l1);
    hi[2 * i]     = *(__nv_bfloat162*)&h0;
    hi[2 * i + 1] = *(__nv_bfloat162*)&h1;
    lo[2 * i]     = *(__nv_bfloat162*)&l0;
    lo[2 * i + 1] = *(__nv_bfloat162*)&l1;
}

// ---------------------------------------------------------------------------
// mma.sync GEMM with 2-stage cp.async pipeline.
// C[M,512] = A[M,512] @ W[512,512]^T + bias, bf16 3-split.
// CTA 128x128, 8 warps (2x4), warp tile 64x32, BK=32.
// ---------------------------------------------------------------------------
#define TSTRIDE 80
#define TILE_B  (128 * TSTRIDE)    // 10240
#define GSTAGE  (4 * TILE_B)       // 40960
#define GEMM_SMEM (2 * GSTAGE)     // 81920

template<int MODE>
__global__ __launch_bounds__(256) void gemm_mma_kernel(
    const __nv_bfloat16* __restrict__ Ahi, const __nv_bfloat16* __restrict__ Alo,
    const __nv_bfloat16* __restrict__ Bhi, const __nv_bfloat16* __restrict__ Blo,
    const float* __restrict__ bias, float* __restrict__ C,
    __nv_bfloat16* __restrict__ Chi, __nv_bfloat16* __restrict__ Clo)
{
    extern __shared__ __align__(128) char gsm[];
    const uint32_t sb = smem_u32(gsm);

    const int tid = threadIdx.x;
    const int wid = tid >> 5;
    const int lane = tid & 31;
    const int warp_m = wid & 1;
    const int warp_n = wid >> 1;
    const int m0 = blockIdx.y * 128;
    const int n0 = blockIdx.x * 128;

    const uint4* gAh = (const uint4*)Ahi;
    const uint4* gAl = (const uint4*)Alo;
    const uint4* gBh = (const uint4*)Bhi;
    const uint4* gBl = (const uint4*)Blo;

    // per-thread load slots (2 x 4 arrays x 16B)
    const int lrow = tid >> 2;             // 0..63 base row (x2 halves -> 128)
    const int lq   = tid & 3;              // uint4 within 32-k chunk
    const uint32_t lso = (uint32_t)(lrow * TSTRIDE + lq * 16);

    auto issue_stage = [&](int c, int buf) {
        const int kq = c * 4;
        const uint32_t st = sb + buf * GSTAGE;
        #pragma unroll
        for (int half = 0; half < 2; half++) {
            const int row = half * 64 + lrow;
            const uint32_t so = lso + (uint32_t)(half * 64 * TSTRIDE);
            const size_t ga = (size_t)(m0 + row) * 64 + kq + lq;
            const size_t gb = (size_t)(n0 + row) * 64 + kq + lq;
            cp16(st + so,              &gAh[ga]);
            cp16(st + TILE_B + so,     &gAl[ga]);
            cp16(st + 2 * TILE_B + so, &gBh[gb]);
            cp16(st + 3 * TILE_B + so, &gBl[gb]);
        }
        cp_commit();
    };

    float acc[4][4][4];
    #pragma unroll
    for (int i = 0; i < 4; i++)
        #pragma unroll
        for (int j = 0; j < 4; j++)
            #pragma unroll
            for (int r = 0; r < 4; r++)
                acc[i][j][r] = 0.f;

    const uint32_t a_lrow = (uint32_t)(lane & 15);
    const uint32_t a_lcol = (uint32_t)((lane >> 4) * 16);
    const uint32_t b_lrow = (uint32_t)(((lane >> 4) & 1) * 8 + (lane & 7));
    const uint32_t b_lcol = (uint32_t)(((lane >> 3) & 1) * 16);

    issue_stage(0, 0);

    for (int c = 0; c < 16; c++) {
        if (c + 1 < 16) issue_stage(c + 1, (c + 1) & 1);
        if (c + 1 < 16) cp_wait1(); else cp_wait0();
        __syncthreads();

        const uint32_t st = sb + (c & 1) * GSTAGE;
        const uint32_t sAh = st;
        const uint32_t sAl = st + TILE_B;
        const uint32_t sBh = st + 2 * TILE_B;
        const uint32_t sBl = st + 3 * TILE_B;

        #pragma unroll
        for (int ks = 0; ks < 2; ks++) {
            const uint32_t kb = (uint32_t)(ks * 16);
            uint32_t bh[4][2], bl[4][2];
            #pragma unroll
            for (int p = 0; p < 2; p++) {
                const uint32_t boff =
                    (uint32_t)(warp_n * 32 + p * 16 + b_lrow) * TSTRIDE + b_lcol + kb * 2;
                ldsm_x4(bh[2*p][0], bh[2*p][1], bh[2*p+1][0], bh[2*p+1][1], sBh + boff);
                ldsm_x4(bl[2*p][0], bl[2*p][1], bl[2*p+1][0], bl[2*p+1][1], sBl + boff);
            }
            #pragma unroll
            for (int mt = 0; mt < 4; mt++) {
                const uint32_t aoff =
                    (uint32_t)(warp_m * 64 + mt * 16 + a_lrow) * TSTRIDE + a_lcol + kb * 2;
                uint32_t ah0, ah1, ah2, ah3, al0, al1, al2, al3;
                ldsm_x4(ah0, ah1, ah2, ah3, sAh + aoff);
                ldsm_x4(al0, al1, al2, al3, sAl + aoff);
                #pragma unroll
                for (int nt = 0; nt < 4; nt++) {
                    mma_bf16(acc[mt][nt][0], acc[mt][nt][1], acc[mt][nt][2], acc[mt][nt][3],
                             ah0, ah1, ah2, ah3, bh[nt][0], bh[nt][1]);
                    mma_bf16(acc[mt][nt][0], acc[mt][nt][1], acc[mt][nt][2], acc[mt][nt][3],
                             ah0, ah1, ah2, ah3, bl[nt][0], bl[nt][1]);
                    mma_bf16(acc[mt][nt][0], acc[mt][nt][1], acc[mt][nt][2], acc[mt][nt][3],
                             al0, al1, al2, al3, bh[nt][0], bh[nt][1]);
                }
            }
        }
        __syncthreads();
    }

    const int rbase = m0 + warp_m * 64 + (lane >> 2);
    const int cbase = n0 + warp_n * 32 + (lane & 3) * 2;
    #pragma unroll
    for (int mt = 0; mt < 4; mt++) {
        #pragma unroll
        for (int nt = 0; nt < 4; nt++) {
            const int col = cbase + nt * 8;
            const float b0 = bias[col];
            const float b1 = bias[col + 1];
            const int r0 = rbase + mt * 16;
            const float o00 = acc[mt][nt][0] + b0, o01 = acc[mt][nt][1] + b1;
            const float o10 = acc[mt][nt][2] + b0, o11 = acc[mt][nt][3] + b1;
            if (MODE == 0) {
                *(float2*)&C[(size_t)r0 * DD + col]       = make_float2(o00, o01);
                *(float2*)&C[(size_t)(r0 + 8) * DD + col] = make_float2(o10, o11);
            } else {
                uint32_t h0, l0, h1, l1;
                pack_split(o00, o01, h0, l0);
                pack_split(o10, o11, h1, l1);
                *(uint32_t*)&Chi[(size_t)r0 * DD + col]       = h0;
                *(uint32_t*)&Clo[(size_t)r0 * DD + col]       = l0;
                *(uint32_t*)&Chi[(size_t)(r0 + 8) * DD + col] = h1;
                *(uint32_t*)&Clo[(size_t)(r0 + 8) * DD + col] = l1;
            }
        }
    }
}

// ---------------------------------------------------------------------------
// Tensor-core fused relu-normalized attention, 2-stage cp.async K/V pipeline.
// Block: 128 q-rows x 1 head x 1 (t,b); 8 warps, each 16 q-rows.
// V stored naturally; B-fragments for ctx += S*V via ldmatrix.x4.trans.
// ---------------------------------------------------------------------------
#define ASTRIDE 144
#define OQH   0
#define OQL   18432            // 128*144
#define OSTG  36864
#define STGSZ 36864            // 4 x 64*144
#define AK_H  0
#define AK_L  9216
#define AV_H  18432
#define AV_L  27648
#define ATTN_SMEM (OSTG + 2 * STGSZ)   // 110592

__global__ __launch_bounds__(256) void attn_mma_kernel(
    const __nv_bfloat16* __restrict__ qhi, const __nv_bfloat16* __restrict__ qlo,
    const __nv_bfloat16* __restrict__ khi, const __nv_bfloat16* __restrict__ klo,
    const __nv_bfloat16* __restrict__ vhi, const __nv_bfloat16* __restrict__ vlo,
    __nv_bfloat16* __restrict__ ctxhi, __nv_bfloat16* __restrict__ ctxlo)
{
    extern __shared__ __align__(128) char smem_[];
    const uint32_t sb = smem_u32(smem_);

    const int tid = threadIdx.x;
    const int wid = tid >> 5;
    const int lane = tid & 31;
    const int qt = blockIdx.x;      // 0..7
    const int h  = blockIdx.y;      // 0..7
    const int tb = blockIdx.z;      // 0..15
    const size_t rowbase = (size_t)tb * NN;
    const int col0 = h * HDIM;
    const int q0 = qt * 128;
    const int cq8 = col0 >> 3;

    const uint4* gqh = (const uint4*)qhi;
    const uint4* gql = (const uint4*)qlo;
    const uint4* gkh = (const uint4*)khi;
    const uint4* gkl = (const uint4*)klo;
    const uint4* gvh = (const uint4*)vhi;
    const uint4* gvl = (const uint4*)vlo;

    const int lr = tid >> 3;        // 0..31 base row (x2 -> 64)
    const int lch = tid & 7;
    const uint32_t lso = (uint32_t)(lr * ASTRIDE + lch * 16);

    auto issue_stage = [&](int kt, int buf) {
        const uint32_t st = sb + OSTG + buf * STGSZ;
        #pragma unroll
        for (int half = 0; half < 2; half++) {
            const int r = half * 32 + lr;
            const uint32_t so = lso + (uint32_t)(half * 32 * ASTRIDE);
            const size_t g = (rowbase + kt * 64 + r) * 64 + cq8 + lch;
            cp16(st + AK_H + so, &gkh[g]);
            cp16(st + AK_L + so, &gkl[g]);
            cp16(st + AV_H + so, &gvh[g]);
            cp16(st + AV_L + so, &gvl[g]);
        }
        cp_commit();
    };

    issue_stage(0, 0);

    // ---- load Q tile (128 x 64 bf16, hi/lo) while stage 0 is in flight ----
    #pragma unroll
    for (int it = 0; it < 4; it++) {
        const int idx = it * 256 + tid;
        const int r  = idx >> 3;
        const int ch = idx & 7;
        const size_t g = (rowbase + q0 + r) * 64 + cq8 + ch;
        const uint32_t so = (uint32_t)(r * ASTRIDE + ch * 16);
        *(uint4*)(smem_ + OQH + so) = gqh[g];
        *(uint4*)(smem_ + OQL + so) = gql[g];
    }
    __syncthreads();

    const uint32_t a_lrow = (uint32_t)(lane & 15);
    const uint32_t a_lcol = (uint32_t)((lane >> 4) * 16);
    const uint32_t b_lrow = (uint32_t)(((lane >> 4) & 1) * 8 + (lane & 7));
    const uint32_t b_lcol = (uint32_t)(((lane >> 3) & 1) * 16);
    // trans-ldmatrix lane addressing for V ([kk][d] natural layout)
    const uint32_t v_lrow = (uint32_t)(lane & 15);
    const uint32_t v_lcol = (uint32_t)((lane >> 4) * 16);

    uint32_t qh[4][4], ql[4][4];
    #pragma unroll
    for (int ks = 0; ks < 4; ks++) {
        const uint32_t aoff = (uint32_t)(wid * 16 + a_lrow) * ASTRIDE + a_lcol + ks * 32;
        ldsm_x4(qh[ks][0], qh[ks][1], qh[ks][2], qh[ks][3], sb + OQH + aoff);
        ldsm_x4(ql[ks][0], ql[ks][1], ql[ks][2], ql[ks][3], sb + OQL + aoff);
    }

    float acc[8][4];
    #pragma unroll
    for (int i = 0; i < 8; i++)
        #pragma unroll
        for (int j = 0; j < 4; j++)
            acc[i][j] = 0.f;
    float dsum0 = 0.f, dsum1 = 0.f;

    for (int kt = 0; kt < 16; kt++) {
        if (kt + 1 < 16) issue_stage(kt + 1, (kt + 1) & 1);
        if (kt + 1 < 16) cp_wait1(); else cp_wait0();
        __syncthreads();

        const uint32_t st = sb + OSTG + (kt & 1) * STGSZ;

        // ---- phase 1: S = Q K^T (3-split) ----
        float s[8][4];
        #pragma unroll
        for (int i = 0; i < 8; i++)
            #pragma unroll
            for (int j = 0; j < 4; j++)
                s[i][j] = 0.f;

        #pragma unroll
        for (int ks = 0; ks < 4; ks++) {
            #pragma unroll
            for (int p = 0; p < 4; p++) {
                const uint32_t boff = (uint32_t)(p * 16 + b_lrow) * ASTRIDE + b_lcol + ks * 32;
                uint32_t kh0, kh1, kh2, kh3, kl0, kl1, kl2, kl3;
                ldsm_x4(kh0, kh1, kh2, kh3, st + AK_H + boff);
                ldsm_x4(kl0, kl1, kl2, kl3, st + AK_L + boff);
                mma4(s[2*p],     qh[ks], kh0, kh1);
                mma4(s[2*p],     qh[ks], kl0, kl1);
                mma4(s[2*p],     ql[ks], kh0, kh1);
                mma4(s[2*p + 1], qh[ks], kh2, kh3);
                mma4(s[2*p + 1], qh[ks], kl2, kl3);
                mma4(s[2*p + 1], ql[ks], kh2, kh3);
            }
        }

        // ---- relu/scale, denominator, repack as A fragments ----
        #pragma unroll
        for (int nt = 0; nt < 8; nt++) {
            #pragma unroll
            for (int e = 0; e < 4; e++)
                s[nt][e] = fmaxf(s[nt][e] * 0.125f, 0.f);
            dsum0 += s[nt][0] + s[nt][1];
            dsum1 += s[nt][2] + s[nt][3];
        }
        uint32_t ahi[4][4], alo[4][4];
        #pragma unroll
        for (int g = 0; g < 4; g++) {
            pack_split(s[2*g][0],     s[2*g][1],     ahi[g][0], alo[g][0]);
            pack_split(s[2*g][2],     s[2*g][3],     ahi[g][1], alo[g][1]);
            pack_split(s[2*g + 1][0], s[2*g + 1][1], ahi[g][2], alo[g][2]);
            pack_split(s[2*g + 1][2], s[2*g + 1][3], ahi[g][3], alo[g][3]);
        }

        // ---- phase 2: ctx += S V (3-split, V natural + ldmatrix.trans) ----
        #pragma unroll
        for (int g = 0; g < 4; g++) {
            const uint32_t grow = (uint32_t)(g * 16 + v_lrow) * ASTRIDE + v_lcol;
            #pragma unroll
            for (int p = 0; p < 4; p++) {
                const uint32_t vaddr = grow + p * 32;
                uint32_t vh0, vh1, vh2, vh3, vl0, vl1, vl2, vl3;
                ldsm_x4_t(vh0, vh1, vh2, vh3, st + AV_H + vaddr);
                ldsm_x4_t(vl0, vl1, vl2, vl3, st + AV_L + vaddr);
                mma4(acc[2*p],     ahi[g], vh0, vh1);
                mma4(acc[2*p],     ahi[g], vl0, vl1);
                mma4(acc[2*p],     alo[g], vh0, vh1);
                mma4(acc[2*p + 1], ahi[g], vh2, vh3);
                mma4(acc[2*p + 1], ahi[g], vl2, vl3);
                mma4(acc[2*p + 1], alo[g], vh2, vh3);
            }
        }
        __syncthreads();
    }

    // ---- denominator reduce across the quad (cols), normalize, write ----
    dsum0 += __shfl_xor_sync(0xffffffffu, dsum0, 1);
    dsum0 += __shfl_xor_sync(0xffffffffu, dsum0, 2);
    dsum1 += __shfl_xor_sync(0xffffffffu, dsum1, 1);
    dsum1 += __shfl_xor_sync(0xffffffffu, dsum1, 2);
    const float inv0 = 1.f / (dsum0 + EPSV);
    const float inv1 = 1.f / (dsum1 + EPSV);

    const size_t r0 = rowbase + q0 + wid * 16 + (lane >> 2);
    const int ccol = (lane & 3) * 2;
    #pragma unroll
    for (int nt = 0; nt < 8; nt++) {
        const int col = col0 + nt * 8 + ccol;
        uint32_t h0, l0, h1, l1;
        pack_split(acc[nt][0] * inv0, acc[nt][1] * inv0, h0, l0);
        pack_split(acc[nt][2] * inv1, acc[nt][3] * inv1, h1, l1);
        *(uint32_t*)&ctxhi[r0 * DD + col]       = h0;
        *(uint32_t*)&ctxlo[r0 * DD + col]       = l0;
        *(uint32_t*)&ctxhi[(r0 + 8) * DD + col] = h1;
        *(uint32_t*)&ctxlo[(r0 + 8) * DD + col] = l1;
    }
}

// ---------------------------------------------------------------------------
extern "C" void kernel_launch(void* const* d_in, const int* in_sizes, int n_in,
                              void* d_out, int out_size)
{
    (void)in_sizes; (void)n_in; (void)out_size;
    const float* x  = (const float*)d_in[0];
    const float* wq = (const float*)d_in[1];
    const float* bq = (const float*)d_in[2];
    const float* wk = (const float*)d_in[3];
    const float* bk = (const float*)d_in[4];
    const float* wv = (const float*)d_in[5];
    const float* bv = (const float*)d_in[6];
    const float* wo = (const float*)d_in[7];
    const float* bo = (const float*)d_in[8];
    float* out = (float*)d_out;

    void *pqh, *pql, *pkh, *pkl, *pvh, *pvl, *pxh, *pxl, *pch, *pcl, *pwh, *pwl;
    cudaGetSymbolAddress(&pqh, g_qhi);
    cudaGetSymbolAddress(&pql, g_qlo);
    cudaGetSymbolAddress(&pkh, g_khi);
    cudaGetSymbolAddress(&pkl, g_klo);
    cudaGetSymbolAddress(&pvh, g_vhi);
    cudaGetSymbolAddress(&pvl, g_vlo);
    cudaGetSymbolAddress(&pxh, g_xhi);
    cudaGetSymbolAddress(&pxl, g_xlo);
    cudaGetSymbolAddress(&pch, g_ctxhi);
    cudaGetSymbolAddress(&pcl, g_ctxlo);
    cudaGetSymbolAddress(&pwh, g_whi);
    cudaGetSymbolAddress(&pwl, g_wlo);
    __nv_bfloat16* qhi = (__nv_bfloat16*)pqh;
    __nv_bfloat16* qlo = (__nv_bfloat16*)pql;
    __nv_bfloat16* khi = (__nv_bfloat16*)pkh;
    __nv_bfloat16* klo = (__nv_bfloat16*)pkl;
    __nv_bfloat16* vhi = (__nv_bfloat16*)pvh;
    __nv_bfloat16* vlo = (__nv_bfloat16*)pvl;
    __nv_bfloat16* xhi = (__nv_bfloat16*)pxh;
    __nv_bfloat16* xlo = (__nv_bfloat16*)pxl;
    __nv_bfloat16* chi = (__nv_bfloat16*)pch;
    __nv_bfloat16* clo = (__nv_bfloat16*)pcl;
    __nv_bfloat16* whi = (__nv_bfloat16*)pwh;
    __nv_bfloat16* wlo = (__nv_bfloat16*)pwl;

    cudaFuncSetAttribute(attn_mma_kernel,    cudaFuncAttributeMaxDynamicSharedMemorySize, ATTN_SMEM);
    cudaFuncSetAttribute(gemm_mma_kernel<0>, cudaFuncAttributeMaxDynamicSharedMemorySize, GEMM_SMEM);
    cudaFuncSetAttribute(gemm_mma_kernel<1>, cudaFuncAttributeMaxDynamicSharedMemorySize, GEMM_SMEM);

    // fp32 -> bf16 hi/lo splits
    {
        const int n4x = MM * DD / 4;
        convert_split_kernel<<<(n4x + 255) / 256, 256>>>(
            (const float4*)x, (__nv_bfloat162*)xhi, (__nv_bfloat162*)xlo, n4x);
        const int n4w = DD * DD / 4;
        const float* ws[4] = {wq, wk, wv, wo};
        for (int i = 0; i < 4; i++) {
            convert_split_kernel<<<(n4w + 255) / 256, 256>>>(
                (const float4*)ws[i],
                (__nv_bfloat162*)(whi + (size_t)i * DD * DD),
                (__nv_bfloat162*)(wlo + (size_t)i * DD * DD), n4w);
        }
    }

    const dim3 ggrid(DD / 128, MM / 128);   // (4, 128)
    gemm_mma_kernel<1><<<ggrid, 256, GEMM_SMEM>>>(xhi, xlo, whi, wlo, bq, nullptr, qhi, qlo);
    gemm_mma_kernel<1><<<ggrid, 256, GEMM_SMEM>>>(xhi, xlo, whi + (size_t)1 * DD * DD, wlo + (size_t)1 * DD * DD, bk, nullptr, khi, klo);
    gemm_mma_kernel<1><<<ggrid, 256, GEMM_SMEM>>>(xhi, xlo, whi + (size_t)2 * DD * DD, wlo + (size_t)2 * DD * DD, bv, nullptr, vhi, vlo);

    attn_mma_kernel<<<dim3(8, HH, TT * BB), 256, ATTN_SMEM>>>(qhi, qlo, khi, klo, vhi, vlo, chi, clo);

    gemm_mma_kernel<0><<<ggrid, 256, GEMM_SMEM>>>(chi, clo, whi + (size_t)3 * DD * DD, wlo + (size_t)3 * DD * DD, bo, out, nullptr, nullptr);
}

// round 7
// speedup vs baseline: 3.0384x; 1.0866x over previous
#include <cuda_runtime.h>
#include <cuda_bf16.h>
#include <cstdint>

#define TT 4
#define BB 4
#define NN 1024
#define DD 512
#define HH 8
#define HDIM 64
#define MM (TT*BB*NN)   // 16384 total rows
#define EPSV 1e-6f

// ---------------- scratch (device globals: allocation-free rule) ----------------
__device__ __nv_bfloat16 g_qkvhi[3 * MM * DD];   // [q; k; v] hi
__device__ __nv_bfloat16 g_qkvlo[3 * MM * DD];   // [q; k; v] lo
__device__ __nv_bfloat16 g_xhi[MM * DD];
__device__ __nv_bfloat16 g_xlo[MM * DD];
__device__ __nv_bfloat16 g_ctxhi[MM * DD];
__device__ __nv_bfloat16 g_ctxlo[MM * DD];
__device__ __nv_bfloat16 g_whi[4 * DD * DD];     // [wq; wk; wv; wo] hi
__device__ __nv_bfloat16 g_wlo[4 * DD * DD];
__device__ float g_bias[3 * DD];                 // [bq; bk; bv]

// ---------------- PTX helpers (base ISA: ldmatrix + mma.sync + cp.async) ------
__device__ __forceinline__ uint32_t smem_u32(const void* p) {
    uint32_t a;
    asm("{ .reg .u64 t; cvta.to.shared.u64 t, %1; cvt.u32.u64 %0, t; }" : "=r"(a) : "l"(p));
    return a;
}
__device__ __forceinline__ void ldsm_x4(uint32_t& r0, uint32_t& r1, uint32_t& r2, uint32_t& r3,
                                        uint32_t addr) {
    asm volatile("ldmatrix.sync.aligned.m8n8.x4.shared.b16 {%0,%1,%2,%3}, [%4];"
                 : "=r"(r0), "=r"(r1), "=r"(r2), "=r"(r3) : "r"(addr));
}
__device__ __forceinline__ void ldsm_x4_t(uint32_t& r0, uint32_t& r1, uint32_t& r2, uint32_t& r3,
                                          uint32_t addr) {
    asm volatile("ldmatrix.sync.aligned.m8n8.x4.trans.shared.b16 {%0,%1,%2,%3}, [%4];"
                 : "=r"(r0), "=r"(r1), "=r"(r2), "=r"(r3) : "r"(addr));
}
__device__ __forceinline__ void mma_bf16(float& c0, float& c1, float& c2, float& c3,
                                         uint32_t a0, uint32_t a1, uint32_t a2, uint32_t a3,
                                         uint32_t b0, uint32_t b1) {
    asm volatile(
        "mma.sync.aligned.m16n8k16.row.col.f32.bf16.bf16.f32 "
        "{%0,%1,%2,%3}, {%4,%5,%6,%7}, {%8,%9}, {%0,%1,%2,%3};"
        : "+f"(c0), "+f"(c1), "+f"(c2), "+f"(c3)
        : "r"(a0), "r"(a1), "r"(a2), "r"(a3), "r"(b0), "r"(b1));
}
__device__ __forceinline__ void mma4(float* c, const uint32_t* a, uint32_t b0, uint32_t b1) {
    mma_bf16(c[0], c[1], c[2], c[3], a[0], a[1], a[2], a[3], b0, b1);
}
__device__ __forceinline__ void cp16(uint32_t saddr, const void* g) {
    asm volatile("cp.async.cg.shared.global [%0], [%1], 16;" :: "r"(saddr), "l"(g) : "memory");
}
__device__ __forceinline__ void cp_commit() {
    asm volatile("cp.async.commit_group;" ::: "memory");
}
__device__ __forceinline__ void cp_wait1() {
    asm volatile("cp.async.wait_group 1;" ::: "memory");
}
__device__ __forceinline__ void cp_wait0() {
    asm volatile("cp.async.wait_group 0;" ::: "memory");
}
__device__ __forceinline__ void pack_split(float x, float y, uint32_t& hi, uint32_t& lo) {
    __nv_bfloat16 hx = __float2bfloat16(x), hy = __float2bfloat16(y);
    __nv_bfloat162 ph; ph.x = hx; ph.y = hy;
    __nv_bfloat162 pl;
    pl.x = __float2bfloat16(x - __bfloat162float(hx));
    pl.y = __float2bfloat16(y - __bfloat162float(hy));
    hi = *(uint32_t*)&ph;
    lo = *(uint32_t*)&pl;
}

// ---------------- fp32 -> bf16 hi/lo splits ----------------
__global__ __launch_bounds__(256) void convert_split_kernel(
    const float4* __restrict__ src,
    __nv_bfloat162* __restrict__ hi, __nv_bfloat162* __restrict__ lo, int n4)
{
    int i = blockIdx.x * blockDim.x + threadIdx.x;
    if (i >= n4) return;
    float4 v = src[i];
    uint32_t h0, l0, h1, l1;
    pack_split(v.x, v.y, h0, l0);
    pack_split(v.z, v.w, h1, l1);
    hi[2 * i]     = *(__nv_bfloat162*)&h0;
    hi[2 * i + 1] = *(__nv_bfloat162*)&h1;
    lo[2 * i]     = *(__nv_bfloat162*)&l0;
    lo[2 * i + 1] = *(__nv_bfloat162*)&l1;
}

// fused convert of all 4 weights (each DD*DD/4 float4 elements)
__global__ __launch_bounds__(256) void convert_w_kernel(
    const float4* __restrict__ w0, const float4* __restrict__ w1,
    const float4* __restrict__ w2, const float4* __restrict__ w3,
    __nv_bfloat162* __restrict__ hi, __nv_bfloat162* __restrict__ lo)
{
    const int n4seg = DD * DD / 4;
    int i = blockIdx.x * blockDim.x + threadIdx.x;
    if (i >= 4 * n4seg) return;
    const int seg = i / n4seg;
    const int j   = i - seg * n4seg;
    const float4* src = (seg == 0) ? w0 : (seg == 1) ? w1 : (seg == 2) ? w2 : w3;
    float4 v = src[j];
    uint32_t h0, l0, h1, l1;
    pack_split(v.x, v.y, h0, l0);
    pack_split(v.z, v.w, h1, l1);
    hi[2 * i]     = *(__nv_bfloat162*)&h0;
    hi[2 * i + 1] = *(__nv_bfloat162*)&h1;
    lo[2 * i]     = *(__nv_bfloat162*)&l0;
    lo[2 * i + 1] = *(__nv_bfloat162*)&l1;
}

// ---------------------------------------------------------------------------
// mma.sync GEMM with 2-stage cp.async pipeline.
// A is [M,512]; B rows indexed globally by n (supports N=1536 fused QKV).
// MODE 0: fp32 output (N=512). MODE 1: bf16 hi/lo output, segment-relocated.
// CTA 128x128, 8 warps (2x4), warp tile 64x32, BK=32.
// ---------------------------------------------------------------------------
#define TSTRIDE 80
#define TILE_B  (128 * TSTRIDE)    // 10240
#define GSTAGE  (4 * TILE_B)       // 40960
#define GEMM_SMEM (2 * GSTAGE)     // 81920

template<int MODE>
__global__ __launch_bounds__(256, 2) void gemm_mma_kernel(
    const __nv_bfloat16* __restrict__ Ahi, const __nv_bfloat16* __restrict__ Alo,
    const __nv_bfloat16* __restrict__ Bhi, const __nv_bfloat16* __restrict__ Blo,
    const float* __restrict__ bias, float* __restrict__ C,
    __nv_bfloat16* __restrict__ Chi, __nv_bfloat16* __restrict__ Clo)
{
    extern __shared__ __align__(128) char gsm[];
    const uint32_t sb = smem_u32(gsm);

    const int tid = threadIdx.x;
    const int wid = tid >> 5;
    const int lane = tid & 31;
    const int warp_m = wid & 1;
    const int warp_n = wid >> 1;
    const int m0 = blockIdx.y * 128;
    const int n0 = blockIdx.x * 128;   // global column (may exceed 512 in fused mode)

    const uint4* gAh = (const uint4*)Ahi;
    const uint4* gAl = (const uint4*)Alo;
    const uint4* gBh = (const uint4*)Bhi;
    const uint4* gBl = (const uint4*)Blo;

    const int lrow = tid >> 2;
    const int lq   = tid & 3;
    const uint32_t lso = (uint32_t)(lrow * TSTRIDE + lq * 16);

    auto issue_stage = [&](int c, int buf) {
        const int kq = c * 4;
        const uint32_t st = sb + buf * GSTAGE;
        #pragma unroll
        for (int half = 0; half < 2; half++) {
            const int row = half * 64 + lrow;
            const uint32_t so = lso + (uint32_t)(half * 64 * TSTRIDE);
            const size_t ga = (size_t)(m0 + row) * 64 + kq + lq;
            const size_t gb = (size_t)(n0 + row) * 64 + kq + lq;
            cp16(st + so,              &gAh[ga]);
            cp16(st + TILE_B + so,     &gAl[ga]);
            cp16(st + 2 * TILE_B + so, &gBh[gb]);
            cp16(st + 3 * TILE_B + so, &gBl[gb]);
        }
        cp_commit();
    };

    float acc[4][4][4];
    #pragma unroll
    for (int i = 0; i < 4; i++)
        #pragma unroll
        for (int j = 0; j < 4; j++)
            #pragma unroll
            for (int r = 0; r < 4; r++)
                acc[i][j][r] = 0.f;

    const uint32_t a_lrow = (uint32_t)(lane & 15);
    const uint32_t a_lcol = (uint32_t)((lane >> 4) * 16);
    const uint32_t b_lrow = (uint32_t)(((lane >> 4) & 1) * 8 + (lane & 7));
    const uint32_t b_lcol = (uint32_t)(((lane >> 3) & 1) * 16);

    issue_stage(0, 0);

    for (int c = 0; c < 16; c++) {
        if (c + 1 < 16) issue_stage(c + 1, (c + 1) & 1);
        if (c + 1 < 16) cp_wait1(); else cp_wait0();
        __syncthreads();

        const uint32_t st = sb + (c & 1) * GSTAGE;
        const uint32_t sAh = st;
        const uint32_t sAl = st + TILE_B;
        const uint32_t sBh = st + 2 * TILE_B;
        const uint32_t sBl = st + 3 * TILE_B;

        #pragma unroll
        for (int ks = 0; ks < 2; ks++) {
            const uint32_t kb = (uint32_t)(ks * 32);
            uint32_t bh[4][2], bl[4][2];
            #pragma unroll
            for (int p = 0; p < 2; p++) {
                const uint32_t boff =
                    (uint32_t)(warp_n * 32 + p * 16 + b_lrow) * TSTRIDE + b_lcol + kb;
                ldsm_x4(bh[2*p][0], bh[2*p][1], bh[2*p+1][0], bh[2*p+1][1], sBh + boff);
                ldsm_x4(bl[2*p][0], bl[2*p][1], bl[2*p+1][0], bl[2*p+1][1], sBl + boff);
            }
            #pragma unroll
            for (int mt = 0; mt < 4; mt++) {
                const uint32_t aoff =
                    (uint32_t)(warp_m * 64 + mt * 16 + a_lrow) * TSTRIDE + a_lcol + kb;
                uint32_t ah0, ah1, ah2, ah3, al0, al1, al2, al3;
                ldsm_x4(ah0, ah1, ah2, ah3, sAh + aoff);
                ldsm_x4(al0, al1, al2, al3, sAl + aoff);
                #pragma unroll
                for (int nt = 0; nt < 4; nt++) {
                    mma_bf16(acc[mt][nt][0], acc[mt][nt][1], acc[mt][nt][2], acc[mt][nt][3],
                             ah0, ah1, ah2, ah3, bh[nt][0], bh[nt][1]);
                    mma_bf16(acc[mt][nt][0], acc[mt][nt][1], acc[mt][nt][2], acc[mt][nt][3],
                             ah0, ah1, ah2, ah3, bl[nt][0], bl[nt][1]);
                    mma_bf16(acc[mt][nt][0], acc[mt][nt][1], acc[mt][nt][2], acc[mt][nt][3],
                             al0, al1, al2, al3, bh[nt][0], bh[nt][1]);
                }
            }
        }
        __syncthreads();
    }

    // epilogue (segment-relocated for fused QKV when MODE==1)
    const int seg  = n0 >> 9;                       // 0..2 (0 for MODE 0)
    const int nloc = n0 & 511;
    const size_t segoff = (size_t)seg * MM * DD;
    const int rbase = m0 + warp_m * 64 + (lane >> 2);
    const int cbase = nloc + warp_n * 32 + (lane & 3) * 2;
    #pragma unroll
    for (int mt = 0; mt < 4; mt++) {
        #pragma unroll
        for (int nt = 0; nt < 4; nt++) {
            const int col = cbase + nt * 8;
            const float b0 = bias[(n0 & ~511) + col];
            const float b1 = bias[(n0 & ~511) + col + 1];
            const int r0 = rbase + mt * 16;
            const float o00 = acc[mt][nt][0] + b0, o01 = acc[mt][nt][1] + b1;
            const float o10 = acc[mt][nt][2] + b0, o11 = acc[mt][nt][3] + b1;
            if (MODE == 0) {
                *(float2*)&C[(size_t)r0 * DD + col]       = make_float2(o00, o01);
                *(float2*)&C[(size_t)(r0 + 8) * DD + col] = make_float2(o10, o11);
            } else {
                uint32_t h0, l0, h1, l1;
                pack_split(o00, o01, h0, l0);
                pack_split(o10, o11, h1, l1);
                *(uint32_t*)&Chi[segoff + (size_t)r0 * DD + col]       = h0;
                *(uint32_t*)&Clo[segoff + (size_t)r0 * DD + col]       = l0;
                *(uint32_t*)&Chi[segoff + (size_t)(r0 + 8) * DD + col] = h1;
                *(uint32_t*)&Clo[segoff + (size_t)(r0 + 8) * DD + col] = l1;
            }
        }
    }
}

// ---------------------------------------------------------------------------
// Tensor-core fused relu-normalized attention, 2-stage cp.async K/V pipeline.
// Q staged through buffer 1 then recycled -> smem 73728 -> 2 CTAs/SM.
// ---------------------------------------------------------------------------
#define ASTRIDE 144
#define STGSZ 36864            // 4 x 64*144 (= Q hi+lo size)
#define AK_H  0
#define AK_L  9216
#define AV_H  18432
#define AV_L  27648
#define ATTN_SMEM (2 * STGSZ)  // 73728

__global__ __launch_bounds__(256, 2) void attn_mma_kernel(
    const __nv_bfloat16* __restrict__ qkvhi, const __nv_bfloat16* __restrict__ qkvlo,
    __nv_bfloat16* __restrict__ ctxhi, __nv_bfloat16* __restrict__ ctxlo)
{
    extern __shared__ __align__(128) char smem_[];
    const uint32_t sb = smem_u32(smem_);

    const int tid = threadIdx.x;
    const int wid = tid >> 5;
    const int lane = tid & 31;
    const int qt = blockIdx.x;      // 0..7
    const int h  = blockIdx.y;      // 0..7
    const int tb = blockIdx.z;      // 0..15
    const size_t rowbase = (size_t)tb * NN;
    const int col0 = h * HDIM;
    const int q0 = qt * 128;
    const int cq8 = col0 >> 3;

    const uint4* gqh = (const uint4*)qkvhi;
    const uint4* gql = (const uint4*)qkvlo;
    const uint4* gkh = (const uint4*)(qkvhi + (size_t)MM * DD);
    const uint4* gkl = (const uint4*)(qkvlo + (size_t)MM * DD);
    const uint4* gvh = (const uint4*)(qkvhi + (size_t)2 * MM * DD);
    const uint4* gvl = (const uint4*)(qkvlo + (size_t)2 * MM * DD);

    const int lr = tid >> 3;        // 0..31
    const int lch = tid & 7;
    const uint32_t lso = (uint32_t)(lr * ASTRIDE + lch * 16);

    auto issue_stage = [&](int kt, int buf) {
        const uint32_t st = sb + buf * STGSZ;
        #pragma unroll
        for (int half = 0; half < 2; half++) {
            const int r = half * 32 + lr;
            const uint32_t so = lso + (uint32_t)(half * 32 * ASTRIDE);
            const size_t g = (rowbase + kt * 64 + r) * 64 + cq8 + lch;
            cp16(st + AK_H + so, &gkh[g]);
            cp16(st + AK_L + so, &gkl[g]);
            cp16(st + AV_H + so, &gvh[g]);
            cp16(st + AV_L + so, &gvl[g]);
        }
        cp_commit();
    };

    // ---- Q into buffer 1 via cp.async (hi at +0, lo at +18432) ----
    {
        const uint32_t qb = sb + STGSZ;
        #pragma unroll
        for (int it = 0; it < 4; it++) {
            const int idx = it * 256 + tid;     // 0..1023
            const int r  = idx >> 3;
            const int ch = idx & 7;
            const size_t g = (rowbase + q0 + r) * 64 + cq8 + ch;
            const uint32_t so = (uint32_t)(r * ASTRIDE + ch * 16);
            cp16(qb + so,         &gqh[g]);
            cp16(qb + 18432 + so, &gql[g]);
        }
        cp_commit();
    }
    issue_stage(0, 0);
    cp_wait0();
    __syncthreads();

    const uint32_t a_lrow = (uint32_t)(lane & 15);
    const uint32_t a_lcol = (uint32_t)((lane >> 4) * 16);
    const uint32_t b_lrow = (uint32_t)(((lane >> 4) & 1) * 8 + (lane & 7));
    const uint32_t b_lcol = (uint32_t)(((lane >> 3) & 1) * 16);
    const uint32_t v_lrow = (uint32_t)(lane & 15);
    const uint32_t v_lcol = (uint32_t)((lane >> 4) * 16);

    // ---- Q fragments from buffer 1, then recycle it as a pipeline stage ----
    uint32_t qh[4][4], ql[4][4];
    #pragma unroll
    for (int ks = 0; ks < 4; ks++) {
        const uint32_t aoff = (uint32_t)(wid * 16 + a_lrow) * ASTRIDE + a_lcol + ks * 32;
        ldsm_x4(qh[ks][0], qh[ks][1], qh[ks][2], qh[ks][3], sb + STGSZ + aoff);
        ldsm_x4(ql[ks][0], ql[ks][1], ql[ks][2], ql[ks][3], sb + STGSZ + 18432 + aoff);
    }
    __syncthreads();

    float acc[8][4];
    #pragma unroll
    for (int i = 0; i < 8; i++)
        #pragma unroll
        for (int j = 0; j < 4; j++)
            acc[i][j] = 0.f;
    float dsum0 = 0.f, dsum1 = 0.f;

    for (int kt = 0; kt < 16; kt++) {
        if (kt + 1 < 16) issue_stage(kt + 1, (kt + 1) & 1);
        if (kt + 1 < 16) cp_wait1(); else cp_wait0();
        __syncthreads();

        const uint32_t st = sb + (kt & 1) * STGSZ;

        // ---- phase 1: S = Q K^T (3-split) ----
        float s[8][4];
        #pragma unroll
        for (int i = 0; i < 8; i++)
            #pragma unroll
            for (int j = 0; j < 4; j++)
                s[i][j] = 0.f;

        #pragma unroll
        for (int ks = 0; ks < 4; ks++) {
            #pragma unroll
            for (int p = 0; p < 4; p++) {
                const uint32_t boff = (uint32_t)(p * 16 + b_lrow) * ASTRIDE + b_lcol + ks * 32;
                uint32_t kh0, kh1, kh2, kh3, kl0, kl1, kl2, kl3;
                ldsm_x4(kh0, kh1, kh2, kh3, st + AK_H + boff);
                ldsm_x4(kl0, kl1, kl2, kl3, st + AK_L + boff);
                mma4(s[2*p],     qh[ks], kh0, kh1);
                mma4(s[2*p],     qh[ks], kl0, kl1);
                mma4(s[2*p],     ql[ks], kh0, kh1);
                mma4(s[2*p + 1], qh[ks], kh2, kh3);
                mma4(s[2*p + 1], qh[ks], kl2, kl3);
                mma4(s[2*p + 1], ql[ks], kh2, kh3);
            }
        }

        // ---- relu/scale, denominator, repack as A fragments ----
        #pragma unroll
        for (int nt = 0; nt < 8; nt++) {
            #pragma unroll
            for (int e = 0; e < 4; e++)
                s[nt][e] = fmaxf(s[nt][e] * 0.125f, 0.f);
            dsum0 += s[nt][0] + s[nt][1];
            dsum1 += s[nt][2] + s[nt][3];
        }
        uint32_t ahi[4][4], alo[4][4];
        #pragma unroll
        for (int g = 0; g < 4; g++) {
            pack_split(s[2*g][0],     s[2*g][1],     ahi[g][0], alo[g][0]);
            pack_split(s[2*g][2],     s[2*g][3],     ahi[g][1], alo[g][1]);
            pack_split(s[2*g + 1][0], s[2*g + 1][1], ahi[g][2], alo[g][2]);
            pack_split(s[2*g + 1][2], s[2*g + 1][3], ahi[g][3], alo[g][3]);
        }

        // ---- phase 2: ctx += S V (3-split, V natural + ldmatrix.trans) ----
        #pragma unroll
        for (int g = 0; g < 4; g++) {
            const uint32_t grow = (uint32_t)(g * 16 + v_lrow) * ASTRIDE + v_lcol;
            #pragma unroll
            for (int p = 0; p < 4; p++) {
                const uint32_t vaddr = grow + p * 32;
                uint32_t vh0, vh1, vh2, vh3, vl0, vl1, vl2, vl3;
                ldsm_x4_t(vh0, vh1, vh2, vh3, st + AV_H + vaddr);
                ldsm_x4_t(vl0, vl1, vl2, vl3, st + AV_L + vaddr);
                mma4(acc[2*p],     ahi[g], vh0, vh1);
                mma4(acc[2*p],     ahi[g], vl0, vl1);
                mma4(acc[2*p],     alo[g], vh0, vh1);
                mma4(acc[2*p + 1], ahi[g], vh2, vh3);
                mma4(acc[2*p + 1], ahi[g], vl2, vl3);
                mma4(acc[2*p + 1], alo[g], vh2, vh3);
            }
        }
        __syncthreads();
    }

    // ---- denominator reduce across the quad (cols), normalize, write ----
    dsum0 += __shfl_xor_sync(0xffffffffu, dsum0, 1);
    dsum0 += __shfl_xor_sync(0xffffffffu, dsum0, 2);
    dsum1 += __shfl_xor_sync(0xffffffffu, dsum1, 1);
    dsum1 += __shfl_xor_sync(0xffffffffu, dsum1, 2);
    const float inv0 = 1.f / (dsum0 + EPSV);
    const float inv1 = 1.f / (dsum1 + EPSV);

    const size_t r0 = rowbase + q0 + wid * 16 + (lane >> 2);
    const int ccol = (lane & 3) * 2;
    #pragma unroll
    for (int nt = 0; nt < 8; nt++) {
        const int col = col0 + nt * 8 + ccol;
        uint32_t h0, l0, h1, l1;
        pack_split(acc[nt][0] * inv0, acc[nt][1] * inv0, h0, l0);
        pack_split(acc[nt][2] * inv1, acc[nt][3] * inv1, h1, l1);
        *(uint32_t*)&ctxhi[r0 * DD + col]       = h0;
        *(uint32_t*)&ctxlo[r0 * DD + col]       = l0;
        *(uint32_t*)&ctxhi[(r0 + 8) * DD + col] = h1;
        *(uint32_t*)&ctxlo[(r0 + 8) * DD + col] = l1;
    }
}

// ---------------------------------------------------------------------------
extern "C" void kernel_launch(void* const* d_in, const int* in_sizes, int n_in,
                              void* d_out, int out_size)
{
    (void)in_sizes; (void)n_in; (void)out_size;
    const float* x  = (const float*)d_in[0];
    const float* wq = (const float*)d_in[1];
    const float* bq = (const float*)d_in[2];
    const float* wk = (const float*)d_in[3];
    const float* bk = (const float*)d_in[4];
    const float* wv = (const float*)d_in[5];
    const float* bv = (const float*)d_in[6];
    const float* wo = (const float*)d_in[7];
    const float* bo = (const float*)d_in[8];
    float* out = (float*)d_out;

    void *pqkh, *pqkl, *pxh, *pxl, *pch, *pcl, *pwh, *pwl, *pbias;
    cudaGetSymbolAddress(&pqkh, g_qkvhi);
    cudaGetSymbolAddress(&pqkl, g_qkvlo);
    cudaGetSymbolAddress(&pxh, g_xhi);
    cudaGetSymbolAddress(&pxl, g_xlo);
    cudaGetSymbolAddress(&pch, g_ctxhi);
    cudaGetSymbolAddress(&pcl, g_ctxlo);
    cudaGetSymbolAddress(&pwh, g_whi);
    cudaGetSymbolAddress(&pwl, g_wlo);
    cudaGetSymbolAddress(&pbias, g_bias);
    __nv_bfloat16* qkvhi = (__nv_bfloat16*)pqkh;
    __nv_bfloat16* qkvlo = (__nv_bfloat16*)pqkl;
    __nv_bfloat16* xhi = (__nv_bfloat16*)pxh;
    __nv_bfloat16* xlo = (__nv_bfloat16*)pxl;
    __nv_bfloat16* chi = (__nv_bfloat16*)pch;
    __nv_bfloat16* clo = (__nv_bfloat16*)pcl;
    __nv_bfloat16* whi = (__nv_bfloat16*)pwh;
    __nv_bfloat16* wlo = (__nv_bfloat16*)pwl;
    float* biasqkv = (float*)pbias;

    cudaFuncSetAttribute(attn_mma_kernel,    cudaFuncAttributeMaxDynamicSharedMemorySize, ATTN_SMEM);
    cudaFuncSetAttribute(gemm_mma_kernel<0>, cudaFuncAttributeMaxDynamicSharedMemorySize, GEMM_SMEM);
    cudaFuncSetAttribute(gemm_mma_kernel<1>, cudaFuncAttributeMaxDynamicSharedMemorySize, GEMM_SMEM);

    // bias concat [bq; bk; bv]
    cudaMemcpyAsync(biasqkv,            bq, DD * sizeof(float), cudaMemcpyDeviceToDevice);
    cudaMemcpyAsync(biasqkv + DD,       bk, DD * sizeof(float), cudaMemcpyDeviceToDevice);
    cudaMemcpyAsync(biasqkv + 2 * DD,   bv, DD * sizeof(float), cudaMemcpyDeviceToDevice);

    // fp32 -> bf16 hi/lo splits
    {
        const int n4x = MM * DD / 4;
        convert_split_kernel<<<(n4x + 255) / 256, 256>>>(
            (const float4*)x, (__nv_bfloat162*)xhi, (__nv_bfloat162*)xlo, n4x);
        const int n4wall = 4 * DD * DD / 4;
        convert_w_kernel<<<(n4wall + 255) / 256, 256>>>(
            (const float4*)wq, (const float4*)wk, (const float4*)wv, (const float4*)wo,
            (__nv_bfloat162*)whi, (__nv_bfloat162*)wlo);
    }

    // fused QKV projection: N = 1536
    gemm_mma_kernel<1><<<dim3(12, MM / 128), 256, GEMM_SMEM>>>(
        xhi, xlo, whi, wlo, biasqkv, nullptr, qkvhi, qkvlo);

    attn_mma_kernel<<<dim3(8, HH, TT * BB), 256, ATTN_SMEM>>>(qkvhi, qkvlo, chi, clo);

    // output projection
    gemm_mma_kernel<0><<<dim3(4, MM / 128), 256, GEMM_SMEM>>>(
        chi, clo, whi + (size_t)3 * DD * DD, wlo + (size_t)3 * DD * DD, bo, out, nullptr, nullptr);
}